// round 14
// baseline (speedup 1.0000x reference)
#include <cuda_runtime.h>
#include <cuda_fp16.h>
#include <math.h>
#include <stdint.h>

#define SEQ 1024
#define HDIM 1024
#define NHEADS 16
#define KVHEADS 8
#define HSZ 64
#define NEXP 64
#define TOPK 8
#define CAP 512
#define IDIM 3072
#define EPSF 1e-6f

// ---------------- scratch ----------------
__device__ __half g_x_h[SEQ * HDIM];
__device__ __half g_x_l[SEQ * HDIM];
__device__ float g_qkv[SEQ * 2048];
__device__ float g_q[NHEADS * SEQ * HSZ];
__device__ float g_kT[KVHEADS * HSZ * SEQ];
__device__ float g_v[KVHEADS * SEQ * HSZ];
__device__ float g_scores[(size_t)NHEADS * SEQ * SEQ];
__device__ float g_attn[SEQ * HDIM];
__device__ float g_h1[SEQ * HDIM];
__device__ float g_x2[SEQ * HDIM];
__device__ __half g_x2_h[SEQ * HDIM];
__device__ __half g_x2_l[SEQ * HDIM];
__device__ __half g_hs_h[SEQ * IDIM];
__device__ float g_sharedo[SEQ * HDIM];
__device__ float g_logits[SEQ * NEXP];
__device__ int   g_assign_e[SEQ * TOPK];
__device__ float g_assign_w[SEQ * TOPK];
__device__ int   g_assign_p[SEQ * TOPK];
__device__ int   g_slot_token[NEXP * CAP];
__device__ int   g_count[NEXP];
__device__ __half g_hexp_h[(size_t)NEXP * CAP * IDIM];
__device__ float g_ye[(size_t)NEXP * CAP * HDIM];
// pre-converted fp16 weights
__device__ __half g_wgu_sh_h[(size_t)HDIM * 2 * IDIM];               // interleaved pairs
__device__ __half g_wd_sh_h[(size_t)IDIM * HDIM];
__device__ __half g_wgu_ex_h[(size_t)NEXP * HDIM * 2 * IDIM];        // interleaved pairs
__device__ __half g_wd_ex_h[(size_t)NEXP * IDIM * HDIM];

// ---------------- helpers ----------------
__device__ __forceinline__ uint32_t smem_u32(const void* p) {
    uint32_t a;
    asm("{ .reg .u64 t; cvta.to.shared.u64 t, %1; cvt.u32.u64 %0, t; }" : "=r"(a) : "l"(p));
    return a;
}
__device__ __forceinline__ uint32_t pack_h2(float a, float b) {
    __half2 t = __floats2half2_rn(a, b);
    return *reinterpret_cast<uint32_t*>(&t);
}
__device__ __forceinline__ void splitw_h(float v, __half& h, __half& l) {
    __half hh = __float2half_rn(v);
    h = hh;
    l = __float2half_rn(v - __half2float(hh));
}
__device__ __forceinline__ void split4h(float4 v, uint2& h, uint2& l) {
    __half2 h0 = __floats2half2_rn(v.x, v.y);
    __half2 h1 = __floats2half2_rn(v.z, v.w);
    float2 f0 = __half22float2(h0);
    float2 f1 = __half22float2(h1);
    __half2 l0 = __floats2half2_rn(v.x - f0.x, v.y - f0.y);
    __half2 l1 = __floats2half2_rn(v.z - f1.x, v.w - f1.y);
    h.x = *reinterpret_cast<uint32_t*>(&h0);
    h.y = *reinterpret_cast<uint32_t*>(&h1);
    l.x = *reinterpret_cast<uint32_t*>(&l0);
    l.y = *reinterpret_cast<uint32_t*>(&l1);
}
__device__ __forceinline__ void ldmx4(uint32_t* r, uint32_t addr) {
    asm volatile("ldmatrix.sync.aligned.m8n8.x4.shared.b16 {%0,%1,%2,%3}, [%4];"
                 : "=r"(r[0]), "=r"(r[1]), "=r"(r[2]), "=r"(r[3]) : "r"(addr));
}
__device__ __forceinline__ void ldmx2t(uint32_t* r, uint32_t addr) {
    asm volatile("ldmatrix.sync.aligned.m8n8.x2.trans.shared.b16 {%0,%1}, [%2];"
                 : "=r"(r[0]), "=r"(r[1]) : "r"(addr));
}
__device__ __forceinline__ void mma_h(float* d, const uint32_t* a, const uint32_t* b) {
    asm volatile("mma.sync.aligned.m16n8k16.row.col.f32.f16.f16.f32 "
                 "{%0,%1,%2,%3}, {%4,%5,%6,%7}, {%8,%9}, {%0,%1,%2,%3};"
                 : "+f"(d[0]), "+f"(d[1]), "+f"(d[2]), "+f"(d[3])
                 : "r"(a[0]), "r"(a[1]), "r"(a[2]), "r"(a[3]), "r"(b[0]), "r"(b[1]));
}
__device__ __forceinline__ void cpasync16(uint32_t saddr, const void* g) {
    asm volatile("cp.async.ca.shared.global [%0], [%1], 16;" :: "r"(saddr), "l"(g) : "memory");
}
#define CPCOMMIT() asm volatile("cp.async.commit_group;" ::: "memory")
#define CPWAIT(n)  asm volatile("cp.async.wait_group %0;" :: "n"(n) : "memory")

// ---------------- weight conversion kernels ----------------
// Interleave (a_j, b_j) pairs: in [KG, 2I] fp32 -> out [KG, 2I] fp16 with
// out[k][2j] = in[k][j], out[k][2j+1] = in[k][I+j]. One thread = 4 pairs.
__global__ void conv_inter_kernel(const float* __restrict__ in, __half* __restrict__ out,
                                  int I2, long total) {   // I2 = I/4 groups per row
    long idx = (long)blockIdx.x * 256 + threadIdx.x;
    if (idx >= total) return;
    long k = idx / I2;
    int j4 = (int)(idx % I2) * 4;
    const float* row = in + k * (size_t)(2 * I2 * 4);
    float4 va = *(const float4*)(row + j4);
    float4 vb = *(const float4*)(row + I2 * 4 + j4);
    uint4 o;
    o.x = pack_h2(va.x, vb.x);
    o.y = pack_h2(va.y, vb.y);
    o.z = pack_h2(va.z, vb.z);
    o.w = pack_h2(va.w, vb.w);
    *(uint4*)(out + k * (size_t)(2 * I2 * 4) + 2 * j4) = o;
}
// Plain fp32 -> fp16, 8 elems/thread.
__global__ void conv_plain_kernel(const float* __restrict__ in, __half* __restrict__ out,
                                  long total8) {
    long idx = (long)blockIdx.x * 256 + threadIdx.x;
    if (idx >= total8) return;
    const float4 v0 = *(const float4*)(in + idx * 8);
    const float4 v1 = *(const float4*)(in + idx * 8 + 4);
    uint4 o;
    o.x = pack_h2(v0.x, v0.y);
    o.y = pack_h2(v0.z, v0.w);
    o.z = pack_h2(v1.x, v1.y);
    o.w = pack_h2(v1.z, v1.w);
    *(uint4*)(out + idx * 8) = o;
}

// ======== 1-pass fp16 GEMM, fp16 weights, full cp.async, 3-stage ========
#define APAD 40
#define BPAD 136
#define A_EL (128 * APAD)
#define B_EL (32 * BPAD)
#define SMP_BYTES (3 * (A_EL + B_EL) * 2)

// MODE 0 dense / 1 expert+gather / 2 expert direct.
// FUSE: weights pre-interleaved; epilogue computes a*silu(b) -> fp16 (row width N/2).
template <int MODE, bool FUSE>
__global__ void __launch_bounds__(256, 1) hf_gemm1b(const __half* __restrict__ A,
                                                    const __half* __restrict__ Bh,
                                                    float* __restrict__ C,
                                                    __half* __restrict__ Oh,
                                                    int N, int K) {
    extern __shared__ __align__(16) __half sm[];
    int tid = threadIdx.x, lane = tid & 31, wid = tid >> 5;
    int wm = wid & 1, wn = wid >> 1;

    int e = 0, slot0 = 0, cnt = 128;
    size_t crow0;
    if (MODE == 0) {
        crow0 = (size_t)blockIdx.y * 128;
    } else {
        int t = blockIdx.y;
        e = t >> 2;
        slot0 = (t & 3) * 128;
        int c = g_count[e] - slot0;
        if (c <= 0) return;
        cnt = c < 128 ? c : 128;
        Bh += (size_t)e * K * N;
        crow0 = (size_t)e * CAP + slot0;
    }
    int n0 = blockIdx.x * 128;

    int a_row = tid >> 1;
    int a_q = (tid & 1) * 16;      // 16 halves per thread
    int b_row = tid >> 3;          // 32 k-rows, 8 threads/row
    int b_q = (tid & 7) * 16;      // 16 halves per thread

    bool aok = a_row < cnt;
    size_t a_off;
    if (MODE == 1) {
        int tok = aok ? g_slot_token[e * CAP + slot0 + a_row] : 0;
        a_off = (size_t)tok * K + a_q;
    } else {
        a_off = (crow0 + a_row) * (size_t)K + a_q;
    }
    const __half* aptr = A + a_off;
    const __half* bptr = Bh + (size_t)b_row * N + n0 + b_q;

    float acc[4][4][4];
#pragma unroll
    for (int i = 0; i < 4; i++)
#pragma unroll
        for (int j = 0; j < 4; j++)
#pragma unroll
            for (int v = 0; v < 4; v++) acc[i][j][v] = 0.f;

    uint32_t sbase = smem_u32(sm);
    int oa = a_row * APAD + a_q;
    int ob = b_row * BPAD + b_q;

    // zero inactive A rows once across all 3 stages (never overwritten)
    if (MODE != 0 && !aok) {
        uint4 z = make_uint4(0, 0, 0, 0);
#pragma unroll
        for (int s = 0; s < 3; s++) {
            *(uint4*)(sm + s * A_EL + oa) = z;
            *(uint4*)(sm + s * A_EL + oa + 8) = z;
        }
    }

    auto issue = [&](int s, int k0) {
        if (aok) {
            uint32_t da = sbase + (s * A_EL + oa) * 2;
            cpasync16(da, aptr + k0);
            cpasync16(da + 16, aptr + k0 + 8);
        }
        uint32_t db = sbase + (3 * A_EL + s * B_EL + ob) * 2;
        cpasync16(db, bptr + (size_t)k0 * N);
        cpasync16(db + 16, bptr + (size_t)k0 * N + 8);
        CPCOMMIT();
    };

    int nk = K >> 5;
    issue(0, 0);
    if (nk > 1) { issue(1, 32); CPWAIT(1); }
    else CPWAIT(0);
    __syncthreads();

    for (int c = 0; c < nk; c++) {
        int s = c % 3;
        if (c + 2 < nk) issue((c + 2) % 3, (c + 2) << 5);

        uint32_t ao = sbase + (s * A_EL) * 2;
        uint32_t bo = sbase + (3 * A_EL + s * B_EL) * 2;
#pragma unroll
        for (int ks = 0; ks < 2; ks++) {
            uint32_t ah[4][4], bh[4][2];
#pragma unroll
            for (int i = 0; i < 4; i++) {
                uint32_t off = ((wm * 64 + i * 16 + (lane & 15)) * APAD + ks * 16 + (lane >> 4) * 8) * 2;
                ldmx4(ah[i], ao + off);
            }
#pragma unroll
            for (int j = 0; j < 4; j++) {
                uint32_t off = ((ks * 16 + (lane & 15)) * BPAD + wn * 32 + j * 8) * 2;
                ldmx2t(bh[j], bo + off);
            }
#pragma unroll
            for (int i = 0; i < 4; i++)
#pragma unroll
                for (int j = 0; j < 4; j++) mma_h(acc[i][j], ah[i], bh[j]);
        }

        if (c + 1 < nk) {
            if (c + 2 < nk) CPWAIT(1);
            else CPWAIT(0);
        }
        __syncthreads();
    }

    // ---- epilogue ----
    if (FUSE) {
        int NP = N >> 1;
#pragma unroll
        for (int i = 0; i < 4; i++) {
            int r0 = wm * 64 + i * 16 + (lane >> 2);
#pragma unroll
            for (int j = 0; j < 4; j++) {
                int c0 = n0 + wn * 32 + j * 8 + (lane & 3) * 2;
                int p = c0 >> 1;
                {
                    float a = acc[i][j][0], b = acc[i][j][1];
                    float h = a * (b / (1.f + __expf(-b)));
                    Oh[(crow0 + r0) * (size_t)NP + p] = __float2half_rn(h);
                }
                {
                    float a = acc[i][j][2], b = acc[i][j][3];
                    float h = a * (b / (1.f + __expf(-b)));
                    Oh[(crow0 + r0 + 8) * (size_t)NP + p] = __float2half_rn(h);
                }
            }
        }
    } else {
#pragma unroll
        for (int i = 0; i < 4; i++) {
            int r0 = wm * 64 + i * 16 + (lane >> 2);
#pragma unroll
            for (int j = 0; j < 4; j++) {
                int c0 = n0 + wn * 32 + j * 8 + (lane & 3) * 2;
                float* cp = C + (crow0 + r0) * (size_t)N + c0;
                float* cp2 = C + (crow0 + r0 + 8) * (size_t)N + c0;
                cp[0] = acc[i][j][0];
                cp[1] = acc[i][j][1];
                cp2[0] = acc[i][j][2];
                cp2[1] = acc[i][j][3];
            }
        }
    }
}

// ======== 3-pass fp16 split GEMM, BK=32 (qkv / Wo precision path, as R12) ========
#define OFF_AH(b) ((b) * A_EL)
#define OFF_AL(b) (2 * A_EL + (b) * A_EL)
#define OFF_B(b)  (4 * A_EL + (b) * B_EL)
#define OFF_BL(b) (4 * A_EL + 2 * B_EL + (b) * B_EL)
#define SM3_BYTES ((4 * A_EL + 4 * B_EL) * 2)

template <bool RES, bool ASPLIT>
__global__ void __launch_bounds__(256, 1) hf_gemm3(const void* __restrict__ Av,
                                                   const __half* __restrict__ Alp,
                                                   const float* __restrict__ B,
                                                   float* __restrict__ C,
                                                   const float* __restrict__ res,
                                                   int N, int K) {
    extern __shared__ __align__(16) __half sm[];
    int tid = threadIdx.x, lane = tid & 31, wid = tid >> 5;
    int wm = wid & 1, wn = wid >> 1;
    size_t crow0 = (size_t)blockIdx.y * 128;
    int n0 = blockIdx.x * 128;

    int a_row = tid >> 1;
    int a_q = (tid & 1) * 16;
    int b_row = tid >> 3;
    int b_q = (tid & 7) * 16;

    size_t a_off = (crow0 + a_row) * (size_t)K + a_q;
    const float* aptr_f = (const float*)Av + a_off;
    const __half* aptr_h = (const __half*)Av + a_off;
    const __half* aptr_l = Alp + a_off;
    const float* bptr = B + (size_t)b_row * N + n0 + b_q;

    float acc[4][4][4];
#pragma unroll
    for (int i = 0; i < 4; i++)
#pragma unroll
        for (int j = 0; j < 4; j++)
#pragma unroll
            for (int v = 0; v < 4; v++) acc[i][j][v] = 0.f;

    uint32_t sbase = smem_u32(sm);
    int oa = a_row * APAD + a_q;
    uint32_t aAH0 = sbase + (OFF_AH(0) + oa) * 2;
    uint32_t aAH1 = sbase + (OFF_AH(1) + oa) * 2;
    uint32_t aAL0 = sbase + (OFF_AL(0) + oa) * 2;
    uint32_t aAL1 = sbase + (OFF_AL(1) + oa) * 2;

    auto issue_a = [&](int buf, int k0) {
        if (ASPLIT) {
            uint32_t dh = buf ? aAH1 : aAH0;
            cpasync16(dh, aptr_h + k0);
            cpasync16(dh + 16, aptr_h + k0 + 8);
            uint32_t dl = buf ? aAL1 : aAL0;
            cpasync16(dl, aptr_l + k0);
            cpasync16(dl + 16, aptr_l + k0 + 8);
            CPCOMMIT();
        }
    };

    float4 pa[4];
    float4 pb[4];
    auto load_b = [&](int k0) {
        size_t krow = (size_t)k0 * N;
#pragma unroll
        for (int j = 0; j < 4; j++) pb[j] = *(const float4*)(bptr + krow + j * 4);
    };
    auto store_stage = [&](int buf) {
        if (!ASPLIT) {
            __half* AH = sm + OFF_AH(buf);
            __half* AL = sm + OFF_AL(buf);
#pragma unroll
            for (int j = 0; j < 4; j++) {
                uint2 h, l;
                split4h(pa[j], h, l);
                *(uint2*)(AH + oa + j * 4) = h;
                *(uint2*)(AL + oa + j * 4) = l;
            }
        }
        __half* BP = sm + OFF_B(buf);
        __half* BL = sm + OFF_BL(buf);
        int ob = b_row * BPAD + b_q;
#pragma unroll
        for (int j = 0; j < 4; j++) {
            uint2 h, l;
            split4h(pb[j], h, l);
            *(uint2*)(BP + ob + j * 4) = h;
            *(uint2*)(BL + ob + j * 4) = l;
        }
    };

    issue_a(0, 0);
    if (!ASPLIT) {
#pragma unroll
        for (int j = 0; j < 4; j++) pa[j] = *(const float4*)(aptr_f + j * 4);
    }
    load_b(0);
    store_stage(0);
    if (ASPLIT) CPWAIT(0);
    __syncthreads();

    int nk = K >> 5;
    for (int c = 0; c < nk; c++) {
        int cur = c & 1;
        bool more = (c + 1) < nk;
        if (more) {
            int k1 = (c + 1) << 5;
            issue_a(cur ^ 1, k1);
            if (!ASPLIT) {
#pragma unroll
                for (int j = 0; j < 4; j++) pa[j] = *(const float4*)(aptr_f + k1 + j * 4);
            }
            load_b(k1);
        }

        uint32_t aho = sbase + OFF_AH(cur) * 2;
        uint32_t alo = sbase + OFF_AL(cur) * 2;
        uint32_t bo = sbase + OFF_B(cur) * 2;
        uint32_t blo = sbase + OFF_BL(cur) * 2;
#pragma unroll
        for (int ks = 0; ks < 2; ks++) {
            uint32_t ah[4][4], al[4][4], bh[4][2], bl[4][2];
#pragma unroll
            for (int i = 0; i < 4; i++) {
                uint32_t off = ((wm * 64 + i * 16 + (lane & 15)) * APAD + ks * 16 + (lane >> 4) * 8) * 2;
                ldmx4(ah[i], aho + off);
                ldmx4(al[i], alo + off);
            }
#pragma unroll
            for (int j = 0; j < 4; j++) {
                uint32_t off = ((ks * 16 + (lane & 15)) * BPAD + wn * 32 + j * 8) * 2;
                ldmx2t(bh[j], bo + off);
                ldmx2t(bl[j], blo + off);
            }
#pragma unroll
            for (int i = 0; i < 4; i++)
#pragma unroll
                for (int j = 0; j < 4; j++) mma_h(acc[i][j], ah[i], bh[j]);
#pragma unroll
            for (int i = 0; i < 4; i++)
#pragma unroll
                for (int j = 0; j < 4; j++) mma_h(acc[i][j], al[i], bh[j]);
#pragma unroll
            for (int i = 0; i < 4; i++)
#pragma unroll
                for (int j = 0; j < 4; j++) mma_h(acc[i][j], ah[i], bl[j]);
        }

        if (more) store_stage(cur ^ 1);
        if (ASPLIT && more) CPWAIT(0);
        __syncthreads();
    }

#pragma unroll
    for (int i = 0; i < 4; i++) {
        int r0 = wm * 64 + i * 16 + (lane >> 2);
#pragma unroll
        for (int j = 0; j < 4; j++) {
            int c0 = n0 + wn * 32 + j * 8 + (lane & 3) * 2;
            float* cp = C + (crow0 + r0) * (size_t)N + c0;
            float* cp2 = C + (crow0 + r0 + 8) * (size_t)N + c0;
            if (RES) {
                const float* rp = res + (crow0 + r0) * (size_t)N + c0;
                const float* rp2 = res + (crow0 + r0 + 8) * (size_t)N + c0;
                cp[0] = acc[i][j][0] + rp[0];
                cp[1] = acc[i][j][1] + rp[1];
                cp2[0] = acc[i][j][2] + rp2[0];
                cp2[1] = acc[i][j][3] + rp2[1];
            } else {
                cp[0] = acc[i][j][0];
                cp[1] = acc[i][j][1];
                cp2[0] = acc[i][j][2];
                cp2[1] = acc[i][j][3];
            }
        }
    }
}

// ---------------- rmsnorm ----------------
template <bool OUT32>
__global__ void rmsnorm_kernel(const float* __restrict__ in, const float* __restrict__ w,
                               float* __restrict__ out32,
                               __half* __restrict__ oh, __half* __restrict__ ol) {
    int row = blockIdx.x;
    const float* x = in + (size_t)row * HDIM;
    __shared__ float red[256];
    float s = 0.f;
    for (int i = threadIdx.x; i < HDIM; i += 256) { float v = x[i]; s += v * v; }
    red[threadIdx.x] = s; __syncthreads();
    for (int st = 128; st > 0; st >>= 1) {
        if (threadIdx.x < st) red[threadIdx.x] += red[threadIdx.x + st];
        __syncthreads();
    }
    float inv = rsqrtf(red[0] / (float)HDIM + EPSF);
    for (int i = threadIdx.x; i < HDIM; i += 256) {
        float v = w[i] * x[i] * inv;
        if (OUT32) out32[(size_t)row * HDIM + i] = v;
        __half h, l;
        splitw_h(v, h, l);
        oh[(size_t)row * HDIM + i] = h;
        ol[(size_t)row * HDIM + i] = l;
    }
}

// ---------------- fp32 SGEMM (attention + logits) ----------------
template <bool RES, int KM>
__global__ void sgemm_kernel(const float* __restrict__ A, const float* __restrict__ B,
                             float* __restrict__ C, const float* __restrict__ res,
                             int M, int N, int K, int lda, int ldb, int ldc,
                             long sA, long sB, long sC, int bdiv) {
    int z = blockIdx.z;
    int row0 = blockIdx.y * 128, col0 = blockIdx.x * 128;
    if (KM == 1 && col0 > row0) return;
    int Keff = K;
    if (KM == 2) Keff = (row0 + 128 < K) ? row0 + 128 : K;
    A += (size_t)z * sA;
    B += (size_t)(z / bdiv) * sB;
    C += (size_t)z * sC;
    if (RES) res += (size_t)z * sC;
    __shared__ float As[8][128];
    __shared__ float Bs[8][128];
    int tid = threadIdx.x;
    int tx = tid & 15, ty = tid >> 4;
    int arow = tid >> 1;
    int acol = (tid & 1) * 4;
    int brow = tid >> 5;
    int bcol = (tid & 31) * 4;
    const float* Aptr = A + (size_t)(row0 + arow) * lda + acol;
    const float* Bptr = B + (size_t)brow * ldb + col0 + bcol;
    bool bok = (col0 + bcol) < N;
    float acc[8][8];
#pragma unroll
    for (int i = 0; i < 8; i++)
#pragma unroll
        for (int j = 0; j < 8; j++) acc[i][j] = 0.f;

    for (int k0 = 0; k0 < Keff; k0 += 8) {
        float4 av = *(const float4*)(Aptr + k0);
        As[acol + 0][arow] = av.x;
        As[acol + 1][arow] = av.y;
        As[acol + 2][arow] = av.z;
        As[acol + 3][arow] = av.w;
        float4 bv = make_float4(0.f, 0.f, 0.f, 0.f);
        if (bok) bv = *(const float4*)(Bptr + (size_t)k0 * ldb);
        *(float4*)&Bs[brow][bcol] = bv;
        __syncthreads();
#pragma unroll
        for (int kk = 0; kk < 8; kk++) {
            float am[8], bn[8];
#pragma unroll
            for (int i = 0; i < 8; i++) am[i] = As[kk][ty * 8 + i];
#pragma unroll
            for (int j = 0; j < 8; j++) bn[j] = Bs[kk][tx * 8 + j];
#pragma unroll
            for (int i = 0; i < 8; i++)
#pragma unroll
                for (int j = 0; j < 8; j++) acc[i][j] += am[i] * bn[j];
        }
        __syncthreads();
    }
#pragma unroll
    for (int i = 0; i < 8; i++) {
        int r = row0 + ty * 8 + i;
#pragma unroll
        for (int j = 0; j < 8; j++) {
            int c = col0 + tx * 8 + j;
            if (c < N) {
                float v = acc[i][j];
                if (RES) v += res[(size_t)r * ldc + c];
                C[(size_t)r * ldc + c] = v;
            }
        }
    }
}

// ---------------- RoPE + qk rmsnorm + layout split ----------------
__global__ void rope_qk_kernel(const float* __restrict__ cosb, const float* __restrict__ sinb,
                               const float* __restrict__ qw, const float* __restrict__ kw) {
    int s = blockIdx.x, kv = blockIdx.y;
    int w = threadIdx.x >> 5, lane = threadIdx.x & 31;
    const float* src = g_qkv + (size_t)s * 2048 + kv * 256 + w * 64;
    float x1 = src[lane], x2 = src[lane + 32];
    float o1, o2;
    if (w < 3) {
        float c1 = cosb[s * 64 + lane], s1 = sinb[s * 64 + lane];
        float c2 = cosb[s * 64 + lane + 32], s2 = sinb[s * 64 + lane + 32];
        o1 = x1 * c1 - x2 * s1;
        o2 = x2 * c2 + x1 * s2;
        float ss = o1 * o1 + o2 * o2;
#pragma unroll
        for (int off = 16; off; off >>= 1) ss += __shfl_xor_sync(0xffffffffu, ss, off);
        float inv = rsqrtf(ss / 64.f + EPSF);
        const float* wt = (w < 2) ? qw : kw;
        o1 *= inv * wt[lane];
        o2 *= inv * wt[lane + 32];
    } else {
        o1 = x1; o2 = x2;
    }
    if (w < 2) {
        int head = kv * 2 + w;
        g_q[(size_t)head * 65536 + s * 64 + lane] = o1;
        g_q[(size_t)head * 65536 + s * 64 + lane + 32] = o2;
    } else if (w == 2) {
        g_kT[(size_t)kv * 65536 + lane * 1024 + s] = o1;
        g_kT[(size_t)kv * 65536 + (lane + 32) * 1024 + s] = o2;
    } else {
        g_v[(size_t)kv * 65536 + s * 64 + lane] = o1;
        g_v[(size_t)kv * 65536 + s * 64 + lane + 32] = o2;
    }
}

// ---------------- causal scaled softmax ----------------
__global__ void softmax_kernel() {
    int s = blockIdx.x, h = blockIdx.y;
    float* row = g_scores + ((size_t)h * SEQ + s) * SEQ;
    int n = s + 1;
    __shared__ float red[256];
    int tid = threadIdx.x;
    float m = -INFINITY;
    for (int i = tid; i < n; i += 256) m = fmaxf(m, row[i] * 0.125f);
    red[tid] = m; __syncthreads();
    for (int st = 128; st > 0; st >>= 1) {
        if (tid < st) red[tid] = fmaxf(red[tid], red[tid + st]);
        __syncthreads();
    }
    m = red[0]; __syncthreads();
    float sum = 0.f;
    for (int i = tid; i < n; i += 256) {
        float p = __expf(row[i] * 0.125f - m);
        row[i] = p;
        sum += p;
    }
    red[tid] = sum; __syncthreads();
    for (int st = 128; st > 0; st >>= 1) {
        if (tid < st) red[tid] += red[tid + st];
        __syncthreads();
    }
    float inv = 1.f / red[0];
    for (int i = tid; i < n; i += 256) row[i] *= inv;
    for (int i = n + tid; i < SEQ; i += 256) row[i] = 0.f;
}

// ---------------- gate softmax + top-8 ----------------
__global__ void topk_kernel() {
    int t = blockIdx.x;
    int tid = threadIdx.x;
    __shared__ float gate[NEXP];
    __shared__ float red[NEXP];
    float lg = g_logits[t * NEXP + tid];
    red[tid] = lg; __syncthreads();
    for (int st = 32; st > 0; st >>= 1) {
        if (tid < st) red[tid] = fmaxf(red[tid], red[tid + st]);
        __syncthreads();
    }
    float m = red[0]; __syncthreads();
    float e = __expf(lg - m);
    gate[tid] = e;
    red[tid] = e; __syncthreads();
    for (int st = 32; st > 0; st >>= 1) {
        if (tid < st) red[tid] += red[tid + st];
        __syncthreads();
    }
    float inv = 1.f / red[0];
    __syncthreads();
    gate[tid] = e * inv;
    __syncthreads();
    if (tid == 0) {
        float vals[TOPK];
        int idxs[TOPK];
        float den = 0.f;
        for (int k = 0; k < TOPK; k++) {
            float bv = -INFINITY; int bi = 0;
            for (int i = 0; i < NEXP; i++) {
                float v = gate[i];
                if (v > bv) { bv = v; bi = i; }
            }
            vals[k] = bv; idxs[k] = bi; den += bv;
            gate[bi] = -INFINITY;
        }
        den = fmaxf(den, 1.19209290e-07f);
        for (int k = 0; k < TOPK; k++) {
            g_assign_e[t * TOPK + k] = idxs[k];
            g_assign_w[t * TOPK + k] = vals[k] / den;
        }
    }
}

// ---------------- routing ----------------
__global__ void route_kernel() {
    int e = threadIdx.x;
    int cnt = 0;
    for (int i = 0; i < SEQ * TOPK; i++) {
        if (g_assign_e[i] == e) {
            g_assign_p[i] = cnt;
            if (cnt < CAP) g_slot_token[e * CAP + cnt] = i >> 3;
            cnt++;
        }
    }
    g_count[e] = cnt < CAP ? cnt : CAP;
}

// ---------------- final combine ----------------
__global__ void combine_kernel(float* __restrict__ out) {
    int t = blockIdx.x;
    int tid = threadIdx.x;
    __shared__ float w[TOPK];
    __shared__ int rr[TOPK];
    if (tid < TOPK) {
        int i = t * TOPK + tid;
        int p = g_assign_p[i];
        int e = g_assign_e[i];
        bool valid = p < CAP;
        w[tid] = valid ? g_assign_w[i] : 0.f;
        rr[tid] = e * CAP + (valid ? p : 0);
    }
    __syncthreads();
    for (int h = tid; h < HDIM; h += 256) {
        float v = g_h1[(size_t)t * HDIM + h] + g_sharedo[(size_t)t * HDIM + h];
#pragma unroll
        for (int k = 0; k < TOPK; k++) v += w[k] * g_ye[(size_t)rr[k] * HDIM + h];
        out[(size_t)t * HDIM + h] = v;
    }
}

// ---------------- launch ----------------
extern "C" void kernel_launch(void* const* d_in, const int* in_sizes, int n_in,
                              void* d_out, int out_size) {
    const float* hidden = (const float*)d_in[0];
    const float* cosb = (const float*)d_in[1];
    const float* sinb = (const float*)d_in[2];
    const float* ln1_w = (const float*)d_in[3];
    const float* ln2_w = (const float*)d_in[4];
    const float* Wqkv = (const float*)d_in[5];
    const float* Wo = (const float*)d_in[6];
    const float* qnorm_w = (const float*)d_in[7];
    const float* knorm_w = (const float*)d_in[8];
    const float* Wgu_sh = (const float*)d_in[9];
    const float* Wd_sh = (const float*)d_in[10];
    const float* Wgate = (const float*)d_in[11];
    const float* Wgu_ex = (const float*)d_in[12];
    const float* Wd_ex = (const float*)d_in[13];
    float* out = (float*)d_out;

    float *pqkv, *pq, *pkT, *pv, *pscores, *pattn, *ph1, *px2, *psh, *plog, *pye;
    __half *pxh, *pxl, *px2h, *px2l, *phsh, *pheh;
    __half *pwgsh, *pwdsh, *pwgex, *pwdex;
    cudaGetSymbolAddress((void**)&pxh, g_x_h);
    cudaGetSymbolAddress((void**)&pxl, g_x_l);
    cudaGetSymbolAddress((void**)&pqkv, g_qkv);
    cudaGetSymbolAddress((void**)&pq, g_q);
    cudaGetSymbolAddress((void**)&pkT, g_kT);
    cudaGetSymbolAddress((void**)&pv, g_v);
    cudaGetSymbolAddress((void**)&pscores, g_scores);
    cudaGetSymbolAddress((void**)&pattn, g_attn);
    cudaGetSymbolAddress((void**)&ph1, g_h1);
    cudaGetSymbolAddress((void**)&px2, g_x2);
    cudaGetSymbolAddress((void**)&px2h, g_x2_h);
    cudaGetSymbolAddress((void**)&px2l, g_x2_l);
    cudaGetSymbolAddress((void**)&phsh, g_hs_h);
    cudaGetSymbolAddress((void**)&psh, g_sharedo);
    cudaGetSymbolAddress((void**)&plog, g_logits);
    cudaGetSymbolAddress((void**)&pheh, g_hexp_h);
    cudaGetSymbolAddress((void**)&pye, g_ye);
    cudaGetSymbolAddress((void**)&pwgsh, g_wgu_sh_h);
    cudaGetSymbolAddress((void**)&pwdsh, g_wd_sh_h);
    cudaGetSymbolAddress((void**)&pwgex, g_wgu_ex_h);
    cudaGetSymbolAddress((void**)&pwdex, g_wd_ex_h);

    static int attr_done = 0;
    if (!attr_done) {
        cudaFuncSetAttribute(hf_gemm3<false, true>, cudaFuncAttributeMaxDynamicSharedMemorySize, SM3_BYTES);
        cudaFuncSetAttribute(hf_gemm3<true, false>, cudaFuncAttributeMaxDynamicSharedMemorySize, SM3_BYTES);
        cudaFuncSetAttribute(hf_gemm1b<0, true>, cudaFuncAttributeMaxDynamicSharedMemorySize, SMP_BYTES);
        cudaFuncSetAttribute(hf_gemm1b<0, false>, cudaFuncAttributeMaxDynamicSharedMemorySize, SMP_BYTES);
        cudaFuncSetAttribute(hf_gemm1b<1, true>, cudaFuncAttributeMaxDynamicSharedMemorySize, SMP_BYTES);
        cudaFuncSetAttribute(hf_gemm1b<2, false>, cudaFuncAttributeMaxDynamicSharedMemorySize, SMP_BYTES);
        attr_done = 1;
    }

    // 0. weight conversions (independent; issue first)
    {
        long tot_i_sh = (long)HDIM * (IDIM / 4);                 // 786,432
        conv_inter_kernel<<<(unsigned)((tot_i_sh + 255) / 256), 256>>>(Wgu_sh, pwgsh, IDIM / 4, tot_i_sh);
        long tot_i_ex = (long)NEXP * HDIM * (IDIM / 4);          // 50,331,648
        conv_inter_kernel<<<(unsigned)((tot_i_ex + 255) / 256), 256>>>(Wgu_ex, pwgex, IDIM / 4, tot_i_ex);
        long tot_p_sh = (long)IDIM * HDIM / 8;                   // 393,216
        conv_plain_kernel<<<(unsigned)((tot_p_sh + 255) / 256), 256>>>(Wd_sh, pwdsh, tot_p_sh);
        long tot_p_ex = (long)NEXP * IDIM * HDIM / 8;            // 25,165,824
        conv_plain_kernel<<<(unsigned)((tot_p_ex + 255) / 256), 256>>>(Wd_ex, pwdex, tot_p_ex);
    }

    // 1. x = rmsnorm(hidden, ln1) -> fp16 hi/lo
    rmsnorm_kernel<false><<<SEQ, 256>>>(hidden, ln1_w, nullptr, pxh, pxl);
    // 2. qkv = x @ Wqkv (3-pass)
    hf_gemm3<false, true><<<dim3(16, 8), 256, SM3_BYTES>>>(
        pxh, pxl, Wqkv, pqkv, nullptr, 2048, 1024);
    // 3. rope + qknorm + split
    rope_qk_kernel<<<dim3(SEQ, KVHEADS), 128>>>(cosb, sinb, qnorm_w, knorm_w);
    // 4. scores = q @ k^T (causal block-skip)
    sgemm_kernel<false, 1><<<dim3(8, 8, NHEADS), 256>>>(pq, pkT, pscores, nullptr,
        1024, 1024, 64, 64, 1024, 1024, 65536, 65536, 1048576, 2);
    // 5. causal softmax
    softmax_kernel<<<dim3(SEQ, NHEADS), 256>>>();
    // 6. attn = P @ V (K capped per row-block)
    sgemm_kernel<false, 2><<<dim3(1, 8, NHEADS), 256>>>(pscores, pv, pattn, nullptr,
        1024, 64, 1024, 1024, 64, 1024, 1048576, 65536, 64, 2);
    // 7. h1 = attn @ Wo + hidden (3-pass)
    hf_gemm3<true, false><<<dim3(8, 8), 256, SM3_BYTES>>>(
        pattn, nullptr, Wo, ph1, hidden, 1024, 1024);
    // 8. x2 = rmsnorm(h1, ln2)
    rmsnorm_kernel<true><<<SEQ, 256>>>(ph1, ln2_w, px2, px2h, px2l);
    // 9+10. hs = swiglu(x2 @ Wgu_shared)  [fused, fp16 weights, 3-stage cp.async]
    hf_gemm1b<0, true><<<dim3(48, 8), 256, SMP_BYTES>>>(px2h, pwgsh, nullptr, phsh, 6144, 1024);
    // 11. shared = hs @ Wd_shared
    hf_gemm1b<0, false><<<dim3(8, 8), 256, SMP_BYTES>>>(phsh, pwdsh, psh, nullptr, 1024, 3072);
    // 12. logits = x2 @ Wgate (fp32)
    sgemm_kernel<false, 0><<<dim3(1, 8, 1), 256>>>(px2, Wgate, plog, nullptr,
        1024, 64, 1024, 1024, 64, 64, 0, 0, 0, 1);
    // 13. softmax + top8
    topk_kernel<<<SEQ, 64>>>();
    // 14. routing
    route_kernel<<<1, 64>>>();
    // 15+16. hexp = swiglu(gather(x2) @ Wgu_experts)
    hf_gemm1b<1, true><<<dim3(48, 256), 256, SMP_BYTES>>>(px2h, pwgex, nullptr, pheh, 6144, 1024);
    // 17. ye = hexp @ Wd_experts
    hf_gemm1b<2, false><<<dim3(8, 256), 256, SMP_BYTES>>>(pheh, pwdex, pye, nullptr, 1024, 3072);
    // 18. out = h1 + shared + moe
    combine_kernel<<<SEQ, 256>>>(out);
}

// round 15
// speedup vs baseline: 1.0895x; 1.0895x over previous
#include <cuda_runtime.h>
#include <cuda_fp16.h>
#include <math.h>
#include <stdint.h>

#define SEQ 1024
#define HDIM 1024
#define NHEADS 16
#define KVHEADS 8
#define HSZ 64
#define NEXP 64
#define TOPK 8
#define CAP 512
#define IDIM 3072
#define EPSF 1e-6f

// ---------------- scratch ----------------
__device__ __half g_x_h[SEQ * HDIM];
__device__ __half g_x_l[SEQ * HDIM];
__device__ float g_qkv[SEQ * 2048];
__device__ float g_q[NHEADS * SEQ * HSZ];
__device__ float g_kT[KVHEADS * HSZ * SEQ];
__device__ float g_v[KVHEADS * SEQ * HSZ];
__device__ float g_scores[(size_t)NHEADS * SEQ * SEQ];
__device__ float g_attn[SEQ * HDIM];
__device__ float g_h1[SEQ * HDIM];
__device__ float g_x2[SEQ * HDIM];
__device__ __half g_x2_h[SEQ * HDIM];
__device__ __half g_x2_l[SEQ * HDIM];
__device__ __half g_hs_h[SEQ * IDIM];
__device__ float g_sharedo[SEQ * HDIM];
__device__ float g_logits[SEQ * NEXP];
__device__ int   g_assign_e[SEQ * TOPK];
__device__ float g_assign_w[SEQ * TOPK];
__device__ int   g_assign_p[SEQ * TOPK];
__device__ int   g_slot_token[NEXP * CAP];
__device__ int   g_count[NEXP];
__device__ __half g_hexp_h[(size_t)NEXP * CAP * IDIM];
__device__ float g_ye[(size_t)NEXP * CAP * HDIM];
// pre-converted fp16 weights
__device__ __half g_wgu_sh_h[(size_t)HDIM * 2 * IDIM];
__device__ __half g_wd_sh_h[(size_t)IDIM * HDIM];
__device__ __half g_wgu_ex_h[(size_t)NEXP * HDIM * 2 * IDIM];
__device__ __half g_wd_ex_h[(size_t)NEXP * IDIM * HDIM];

// ---------------- helpers ----------------
__device__ __forceinline__ uint32_t smem_u32(const void* p) {
    uint32_t a;
    asm("{ .reg .u64 t; cvta.to.shared.u64 t, %1; cvt.u32.u64 %0, t; }" : "=r"(a) : "l"(p));
    return a;
}
__device__ __forceinline__ uint32_t pack_h2(float a, float b) {
    __half2 t = __floats2half2_rn(a, b);
    return *reinterpret_cast<uint32_t*>(&t);
}
__device__ __forceinline__ void splitw_h(float v, __half& h, __half& l) {
    __half hh = __float2half_rn(v);
    h = hh;
    l = __float2half_rn(v - __half2float(hh));
}
__device__ __forceinline__ void split4h(float4 v, uint2& h, uint2& l) {
    __half2 h0 = __floats2half2_rn(v.x, v.y);
    __half2 h1 = __floats2half2_rn(v.z, v.w);
    float2 f0 = __half22float2(h0);
    float2 f1 = __half22float2(h1);
    __half2 l0 = __floats2half2_rn(v.x - f0.x, v.y - f0.y);
    __half2 l1 = __floats2half2_rn(v.z - f1.x, v.w - f1.y);
    h.x = *reinterpret_cast<uint32_t*>(&h0);
    h.y = *reinterpret_cast<uint32_t*>(&h1);
    l.x = *reinterpret_cast<uint32_t*>(&l0);
    l.y = *reinterpret_cast<uint32_t*>(&l1);
}
__device__ __forceinline__ void ldmx4(uint32_t* r, uint32_t addr) {
    asm volatile("ldmatrix.sync.aligned.m8n8.x4.shared.b16 {%0,%1,%2,%3}, [%4];"
                 : "=r"(r[0]), "=r"(r[1]), "=r"(r[2]), "=r"(r[3]) : "r"(addr));
}
__device__ __forceinline__ void ldmx2t(uint32_t* r, uint32_t addr) {
    asm volatile("ldmatrix.sync.aligned.m8n8.x2.trans.shared.b16 {%0,%1}, [%2];"
                 : "=r"(r[0]), "=r"(r[1]) : "r"(addr));
}
__device__ __forceinline__ void mma_h(float* d, const uint32_t* a, const uint32_t* b) {
    asm volatile("mma.sync.aligned.m16n8k16.row.col.f32.f16.f16.f32 "
                 "{%0,%1,%2,%3}, {%4,%5,%6,%7}, {%8,%9}, {%0,%1,%2,%3};"
                 : "+f"(d[0]), "+f"(d[1]), "+f"(d[2]), "+f"(d[3])
                 : "r"(a[0]), "r"(a[1]), "r"(a[2]), "r"(a[3]), "r"(b[0]), "r"(b[1]));
}
__device__ __forceinline__ void cpasync16(uint32_t saddr, const void* g) {
    asm volatile("cp.async.ca.shared.global [%0], [%1], 16;" :: "r"(saddr), "l"(g) : "memory");
}
#define CPCOMMIT() asm volatile("cp.async.commit_group;" ::: "memory")
#define CPWAIT(n)  asm volatile("cp.async.wait_group %0;" :: "n"(n) : "memory")

// ---------------- weight conversion kernels ----------------
__global__ void conv_inter_kernel(const float* __restrict__ in, __half* __restrict__ out,
                                  int I2, long total) {
    long idx = (long)blockIdx.x * 256 + threadIdx.x;
    if (idx >= total) return;
    long k = idx / I2;
    int j4 = (int)(idx % I2) * 4;
    const float* row = in + k * (size_t)(2 * I2 * 4);
    float4 va = *(const float4*)(row + j4);
    float4 vb = *(const float4*)(row + I2 * 4 + j4);
    uint4 o;
    o.x = pack_h2(va.x, vb.x);
    o.y = pack_h2(va.y, vb.y);
    o.z = pack_h2(va.z, vb.z);
    o.w = pack_h2(va.w, vb.w);
    *(uint4*)(out + k * (size_t)(2 * I2 * 4) + 2 * j4) = o;
}
__global__ void conv_plain_kernel(const float* __restrict__ in, __half* __restrict__ out,
                                  long total8) {
    long idx = (long)blockIdx.x * 256 + threadIdx.x;
    if (idx >= total8) return;
    const float4 v0 = *(const float4*)(in + idx * 8);
    const float4 v1 = *(const float4*)(in + idx * 8 + 4);
    uint4 o;
    o.x = pack_h2(v0.x, v0.y);
    o.y = pack_h2(v0.z, v0.w);
    o.z = pack_h2(v1.x, v1.y);
    o.w = pack_h2(v1.z, v1.w);
    *(uint4*)(out + idx * 8) = o;
}

// ======== 1-pass fp16 GEMM, fp16 weights, full cp.async, 3-stage, 2 CTAs/SM ========
#define APAD 40
#define BPAD 136
#define A_EL (128 * APAD)
#define B_EL (32 * BPAD)
#define SMP_BYTES (3 * (A_EL + B_EL) * 2)

template <int MODE, bool FUSE>
__global__ void __launch_bounds__(256, 2) hf_gemm1b(const __half* __restrict__ A,
                                                    const __half* __restrict__ Bh,
                                                    float* __restrict__ C,
                                                    __half* __restrict__ Oh,
                                                    int N, int K) {
    extern __shared__ __align__(16) __half sm[];
    int tid = threadIdx.x, lane = tid & 31, wid = tid >> 5;
    int wm = wid & 1, wn = wid >> 1;

    int e = 0, slot0 = 0, cnt = 128;
    size_t crow0;
    if (MODE == 0) {
        crow0 = (size_t)blockIdx.y * 128;
    } else {
        int t = blockIdx.y;
        e = t >> 2;
        slot0 = (t & 3) * 128;
        int c = g_count[e] - slot0;
        if (c <= 0) return;
        cnt = c < 128 ? c : 128;
        Bh += (size_t)e * K * N;
        crow0 = (size_t)e * CAP + slot0;
    }
    int n0 = blockIdx.x * 128;

    int a_row = tid >> 1;
    int a_q = (tid & 1) * 16;
    int b_row = tid >> 3;
    int b_q = (tid & 7) * 16;

    bool aok = a_row < cnt;
    size_t a_off;
    if (MODE == 1) {
        int tok = aok ? g_slot_token[e * CAP + slot0 + a_row] : 0;
        a_off = (size_t)tok * K + a_q;
    } else {
        a_off = (crow0 + a_row) * (size_t)K + a_q;
    }
    const __half* aptr = A + a_off;
    const __half* bptr = Bh + (size_t)b_row * N + n0 + b_q;

    float acc[4][4][4];
#pragma unroll
    for (int i = 0; i < 4; i++)
#pragma unroll
        for (int j = 0; j < 4; j++)
#pragma unroll
            for (int v = 0; v < 4; v++) acc[i][j][v] = 0.f;

    uint32_t sbase = smem_u32(sm);
    int oa = a_row * APAD + a_q;
    int ob = b_row * BPAD + b_q;

    if (MODE != 0 && !aok) {
        uint4 z = make_uint4(0, 0, 0, 0);
#pragma unroll
        for (int s = 0; s < 3; s++) {
            *(uint4*)(sm + s * A_EL + oa) = z;
            *(uint4*)(sm + s * A_EL + oa + 8) = z;
        }
    }

    auto issue = [&](int s, int k0) {
        if (aok) {
            uint32_t da = sbase + (s * A_EL + oa) * 2;
            cpasync16(da, aptr + k0);
            cpasync16(da + 16, aptr + k0 + 8);
        }
        uint32_t db = sbase + (3 * A_EL + s * B_EL + ob) * 2;
        cpasync16(db, bptr + (size_t)k0 * N);
        cpasync16(db + 16, bptr + (size_t)k0 * N + 8);
        CPCOMMIT();
    };

    int nk = K >> 5;
    issue(0, 0);
    if (nk > 1) { issue(1, 32); CPWAIT(1); }
    else CPWAIT(0);
    __syncthreads();

    for (int c = 0; c < nk; c++) {
        int s = c % 3;
        if (c + 2 < nk) issue((c + 2) % 3, (c + 2) << 5);

        uint32_t ao = sbase + (s * A_EL) * 2;
        uint32_t bo = sbase + (3 * A_EL + s * B_EL) * 2;
#pragma unroll
        for (int ks = 0; ks < 2; ks++) {
            uint32_t ah[4][4], bh[4][2];
#pragma unroll
            for (int i = 0; i < 4; i++) {
                uint32_t off = ((wm * 64 + i * 16 + (lane & 15)) * APAD + ks * 16 + (lane >> 4) * 8) * 2;
                ldmx4(ah[i], ao + off);
            }
#pragma unroll
            for (int j = 0; j < 4; j++) {
                uint32_t off = ((ks * 16 + (lane & 15)) * BPAD + wn * 32 + j * 8) * 2;
                ldmx2t(bh[j], bo + off);
            }
#pragma unroll
            for (int i = 0; i < 4; i++)
#pragma unroll
                for (int j = 0; j < 4; j++) mma_h(acc[i][j], ah[i], bh[j]);
        }

        if (c + 1 < nk) {
            if (c + 2 < nk) CPWAIT(1);
            else CPWAIT(0);
        }
        __syncthreads();
    }

    // ---- epilogue ----
    if (FUSE) {
        int NP = N >> 1;
#pragma unroll
        for (int i = 0; i < 4; i++) {
            int r0 = wm * 64 + i * 16 + (lane >> 2);
#pragma unroll
            for (int j = 0; j < 4; j++) {
                int c0 = n0 + wn * 32 + j * 8 + (lane & 3) * 2;
                int p = c0 >> 1;
                {
                    float a = acc[i][j][0], b = acc[i][j][1];
                    float h = a * (b / (1.f + __expf(-b)));
                    Oh[(crow0 + r0) * (size_t)NP + p] = __float2half_rn(h);
                }
                {
                    float a = acc[i][j][2], b = acc[i][j][3];
                    float h = a * (b / (1.f + __expf(-b)));
                    Oh[(crow0 + r0 + 8) * (size_t)NP + p] = __float2half_rn(h);
                }
            }
        }
    } else {
#pragma unroll
        for (int i = 0; i < 4; i++) {
            int r0 = wm * 64 + i * 16 + (lane >> 2);
#pragma unroll
            for (int j = 0; j < 4; j++) {
                int c0 = n0 + wn * 32 + j * 8 + (lane & 3) * 2;
                float* cp = C + (crow0 + r0) * (size_t)N + c0;
                float* cp2 = C + (crow0 + r0 + 8) * (size_t)N + c0;
                cp[0] = acc[i][j][0];
                cp[1] = acc[i][j][1];
                cp2[0] = acc[i][j][2];
                cp2[1] = acc[i][j][3];
            }
        }
    }
}

// ======== 3-pass fp16 split GEMM, BK=32 (qkv / Wo precision path) ========
#define OFF_AH(b) ((b) * A_EL)
#define OFF_AL(b) (2 * A_EL + (b) * A_EL)
#define OFF_B(b)  (4 * A_EL + (b) * B_EL)
#define OFF_BL(b) (4 * A_EL + 2 * B_EL + (b) * B_EL)
#define SM3_BYTES ((4 * A_EL + 4 * B_EL) * 2)

template <bool RES, bool ASPLIT>
__global__ void __launch_bounds__(256, 1) hf_gemm3(const void* __restrict__ Av,
                                                   const __half* __restrict__ Alp,
                                                   const float* __restrict__ B,
                                                   float* __restrict__ C,
                                                   const float* __restrict__ res,
                                                   int N, int K) {
    extern __shared__ __align__(16) __half sm[];
    int tid = threadIdx.x, lane = tid & 31, wid = tid >> 5;
    int wm = wid & 1, wn = wid >> 1;
    size_t crow0 = (size_t)blockIdx.y * 128;
    int n0 = blockIdx.x * 128;

    int a_row = tid >> 1;
    int a_q = (tid & 1) * 16;
    int b_row = tid >> 3;
    int b_q = (tid & 7) * 16;

    size_t a_off = (crow0 + a_row) * (size_t)K + a_q;
    const float* aptr_f = (const float*)Av + a_off;
    const __half* aptr_h = (const __half*)Av + a_off;
    const __half* aptr_l = Alp + a_off;
    const float* bptr = B + (size_t)b_row * N + n0 + b_q;

    float acc[4][4][4];
#pragma unroll
    for (int i = 0; i < 4; i++)
#pragma unroll
        for (int j = 0; j < 4; j++)
#pragma unroll
            for (int v = 0; v < 4; v++) acc[i][j][v] = 0.f;

    uint32_t sbase = smem_u32(sm);
    int oa = a_row * APAD + a_q;
    uint32_t aAH0 = sbase + (OFF_AH(0) + oa) * 2;
    uint32_t aAH1 = sbase + (OFF_AH(1) + oa) * 2;
    uint32_t aAL0 = sbase + (OFF_AL(0) + oa) * 2;
    uint32_t aAL1 = sbase + (OFF_AL(1) + oa) * 2;

    auto issue_a = [&](int buf, int k0) {
        if (ASPLIT) {
            uint32_t dh = buf ? aAH1 : aAH0;
            cpasync16(dh, aptr_h + k0);
            cpasync16(dh + 16, aptr_h + k0 + 8);
            uint32_t dl = buf ? aAL1 : aAL0;
            cpasync16(dl, aptr_l + k0);
            cpasync16(dl + 16, aptr_l + k0 + 8);
            CPCOMMIT();
        }
    };

    float4 pa[4];
    float4 pb[4];
    auto load_b = [&](int k0) {
        size_t krow = (size_t)k0 * N;
#pragma unroll
        for (int j = 0; j < 4; j++) pb[j] = *(const float4*)(bptr + krow + j * 4);
    };
    auto store_stage = [&](int buf) {
        if (!ASPLIT) {
            __half* AH = sm + OFF_AH(buf);
            __half* AL = sm + OFF_AL(buf);
#pragma unroll
            for (int j = 0; j < 4; j++) {
                uint2 h, l;
                split4h(pa[j], h, l);
                *(uint2*)(AH + oa + j * 4) = h;
                *(uint2*)(AL + oa + j * 4) = l;
            }
        }
        __half* BP = sm + OFF_B(buf);
        __half* BL = sm + OFF_BL(buf);
        int ob = b_row * BPAD + b_q;
#pragma unroll
        for (int j = 0; j < 4; j++) {
            uint2 h, l;
            split4h(pb[j], h, l);
            *(uint2*)(BP + ob + j * 4) = h;
            *(uint2*)(BL + ob + j * 4) = l;
        }
    };

    issue_a(0, 0);
    if (!ASPLIT) {
#pragma unroll
        for (int j = 0; j < 4; j++) pa[j] = *(const float4*)(aptr_f + j * 4);
    }
    load_b(0);
    store_stage(0);
    if (ASPLIT) CPWAIT(0);
    __syncthreads();

    int nk = K >> 5;
    for (int c = 0; c < nk; c++) {
        int cur = c & 1;
        bool more = (c + 1) < nk;
        if (more) {
            int k1 = (c + 1) << 5;
            issue_a(cur ^ 1, k1);
            if (!ASPLIT) {
#pragma unroll
                for (int j = 0; j < 4; j++) pa[j] = *(const float4*)(aptr_f + k1 + j * 4);
            }
            load_b(k1);
        }

        uint32_t aho = sbase + OFF_AH(cur) * 2;
        uint32_t alo = sbase + OFF_AL(cur) * 2;
        uint32_t bo = sbase + OFF_B(cur) * 2;
        uint32_t blo = sbase + OFF_BL(cur) * 2;
#pragma unroll
        for (int ks = 0; ks < 2; ks++) {
            uint32_t ah[4][4], al[4][4], bh[4][2], bl[4][2];
#pragma unroll
            for (int i = 0; i < 4; i++) {
                uint32_t off = ((wm * 64 + i * 16 + (lane & 15)) * APAD + ks * 16 + (lane >> 4) * 8) * 2;
                ldmx4(ah[i], aho + off);
                ldmx4(al[i], alo + off);
            }
#pragma unroll
            for (int j = 0; j < 4; j++) {
                uint32_t off = ((ks * 16 + (lane & 15)) * BPAD + wn * 32 + j * 8) * 2;
                ldmx2t(bh[j], bo + off);
                ldmx2t(bl[j], blo + off);
            }
#pragma unroll
            for (int i = 0; i < 4; i++)
#pragma unroll
                for (int j = 0; j < 4; j++) mma_h(acc[i][j], ah[i], bh[j]);
#pragma unroll
            for (int i = 0; i < 4; i++)
#pragma unroll
                for (int j = 0; j < 4; j++) mma_h(acc[i][j], al[i], bh[j]);
#pragma unroll
            for (int i = 0; i < 4; i++)
#pragma unroll
                for (int j = 0; j < 4; j++) mma_h(acc[i][j], ah[i], bl[j]);
        }

        if (more) store_stage(cur ^ 1);
        if (ASPLIT && more) CPWAIT(0);
        __syncthreads();
    }

#pragma unroll
    for (int i = 0; i < 4; i++) {
        int r0 = wm * 64 + i * 16 + (lane >> 2);
#pragma unroll
        for (int j = 0; j < 4; j++) {
            int c0 = n0 + wn * 32 + j * 8 + (lane & 3) * 2;
            float* cp = C + (crow0 + r0) * (size_t)N + c0;
            float* cp2 = C + (crow0 + r0 + 8) * (size_t)N + c0;
            if (RES) {
                const float* rp = res + (crow0 + r0) * (size_t)N + c0;
                const float* rp2 = res + (crow0 + r0 + 8) * (size_t)N + c0;
                cp[0] = acc[i][j][0] + rp[0];
                cp[1] = acc[i][j][1] + rp[1];
                cp2[0] = acc[i][j][2] + rp2[0];
                cp2[1] = acc[i][j][3] + rp2[1];
            } else {
                cp[0] = acc[i][j][0];
                cp[1] = acc[i][j][1];
                cp2[0] = acc[i][j][2];
                cp2[1] = acc[i][j][3];
            }
        }
    }
}

// ---------------- rmsnorm ----------------
template <bool OUT32>
__global__ void rmsnorm_kernel(const float* __restrict__ in, const float* __restrict__ w,
                               float* __restrict__ out32,
                               __half* __restrict__ oh, __half* __restrict__ ol) {
    int row = blockIdx.x;
    const float* x = in + (size_t)row * HDIM;
    __shared__ float red[256];
    float s = 0.f;
    for (int i = threadIdx.x; i < HDIM; i += 256) { float v = x[i]; s += v * v; }
    red[threadIdx.x] = s; __syncthreads();
    for (int st = 128; st > 0; st >>= 1) {
        if (threadIdx.x < st) red[threadIdx.x] += red[threadIdx.x + st];
        __syncthreads();
    }
    float inv = rsqrtf(red[0] / (float)HDIM + EPSF);
    for (int i = threadIdx.x; i < HDIM; i += 256) {
        float v = w[i] * x[i] * inv;
        if (OUT32) out32[(size_t)row * HDIM + i] = v;
        __half h, l;
        splitw_h(v, h, l);
        oh[(size_t)row * HDIM + i] = h;
        ol[(size_t)row * HDIM + i] = l;
    }
}

// ---------------- fp32 SGEMM (attention + logits) ----------------
template <bool RES, int KM>
__global__ void sgemm_kernel(const float* __restrict__ A, const float* __restrict__ B,
                             float* __restrict__ C, const float* __restrict__ res,
                             int M, int N, int K, int lda, int ldb, int ldc,
                             long sA, long sB, long sC, int bdiv) {
    int z = blockIdx.z;
    int row0 = blockIdx.y * 128, col0 = blockIdx.x * 128;
    if (KM == 1 && col0 > row0) return;
    int Keff = K;
    if (KM == 2) Keff = (row0 + 128 < K) ? row0 + 128 : K;
    A += (size_t)z * sA;
    B += (size_t)(z / bdiv) * sB;
    C += (size_t)z * sC;
    if (RES) res += (size_t)z * sC;
    __shared__ float As[8][128];
    __shared__ float Bs[8][128];
    int tid = threadIdx.x;
    int tx = tid & 15, ty = tid >> 4;
    int arow = tid >> 1;
    int acol = (tid & 1) * 4;
    int brow = tid >> 5;
    int bcol = (tid & 31) * 4;
    const float* Aptr = A + (size_t)(row0 + arow) * lda + acol;
    const float* Bptr = B + (size_t)brow * ldb + col0 + bcol;
    bool bok = (col0 + bcol) < N;
    float acc[8][8];
#pragma unroll
    for (int i = 0; i < 8; i++)
#pragma unroll
        for (int j = 0; j < 8; j++) acc[i][j] = 0.f;

    for (int k0 = 0; k0 < Keff; k0 += 8) {
        float4 av = *(const float4*)(Aptr + k0);
        As[acol + 0][arow] = av.x;
        As[acol + 1][arow] = av.y;
        As[acol + 2][arow] = av.z;
        As[acol + 3][arow] = av.w;
        float4 bv = make_float4(0.f, 0.f, 0.f, 0.f);
        if (bok) bv = *(const float4*)(Bptr + (size_t)k0 * ldb);
        *(float4*)&Bs[brow][bcol] = bv;
        __syncthreads();
#pragma unroll
        for (int kk = 0; kk < 8; kk++) {
            float am[8], bn[8];
#pragma unroll
            for (int i = 0; i < 8; i++) am[i] = As[kk][ty * 8 + i];
#pragma unroll
            for (int j = 0; j < 8; j++) bn[j] = Bs[kk][tx * 8 + j];
#pragma unroll
            for (int i = 0; i < 8; i++)
#pragma unroll
                for (int j = 0; j < 8; j++) acc[i][j] += am[i] * bn[j];
        }
        __syncthreads();
    }
#pragma unroll
    for (int i = 0; i < 8; i++) {
        int r = row0 + ty * 8 + i;
#pragma unroll
        for (int j = 0; j < 8; j++) {
            int c = col0 + tx * 8 + j;
            if (c < N) {
                float v = acc[i][j];
                if (RES) v += res[(size_t)r * ldc + c];
                C[(size_t)r * ldc + c] = v;
            }
        }
    }
}

// ---------------- RoPE + qk rmsnorm + layout split ----------------
__global__ void rope_qk_kernel(const float* __restrict__ cosb, const float* __restrict__ sinb,
                               const float* __restrict__ qw, const float* __restrict__ kw) {
    int s = blockIdx.x, kv = blockIdx.y;
    int w = threadIdx.x >> 5, lane = threadIdx.x & 31;
    const float* src = g_qkv + (size_t)s * 2048 + kv * 256 + w * 64;
    float x1 = src[lane], x2 = src[lane + 32];
    float o1, o2;
    if (w < 3) {
        float c1 = cosb[s * 64 + lane], s1 = sinb[s * 64 + lane];
        float c2 = cosb[s * 64 + lane + 32], s2 = sinb[s * 64 + lane + 32];
        o1 = x1 * c1 - x2 * s1;
        o2 = x2 * c2 + x1 * s2;
        float ss = o1 * o1 + o2 * o2;
#pragma unroll
        for (int off = 16; off; off >>= 1) ss += __shfl_xor_sync(0xffffffffu, ss, off);
        float inv = rsqrtf(ss / 64.f + EPSF);
        const float* wt = (w < 2) ? qw : kw;
        o1 *= inv * wt[lane];
        o2 *= inv * wt[lane + 32];
    } else {
        o1 = x1; o2 = x2;
    }
    if (w < 2) {
        int head = kv * 2 + w;
        g_q[(size_t)head * 65536 + s * 64 + lane] = o1;
        g_q[(size_t)head * 65536 + s * 64 + lane + 32] = o2;
    } else if (w == 2) {
        g_kT[(size_t)kv * 65536 + lane * 1024 + s] = o1;
        g_kT[(size_t)kv * 65536 + (lane + 32) * 1024 + s] = o2;
    } else {
        g_v[(size_t)kv * 65536 + s * 64 + lane] = o1;
        g_v[(size_t)kv * 65536 + s * 64 + lane + 32] = o2;
    }
}

// ---------------- causal scaled softmax ----------------
__global__ void softmax_kernel() {
    int s = blockIdx.x, h = blockIdx.y;
    float* row = g_scores + ((size_t)h * SEQ + s) * SEQ;
    int n = s + 1;
    __shared__ float red[256];
    int tid = threadIdx.x;
    float m = -INFINITY;
    for (int i = tid; i < n; i += 256) m = fmaxf(m, row[i] * 0.125f);
    red[tid] = m; __syncthreads();
    for (int st = 128; st > 0; st >>= 1) {
        if (tid < st) red[tid] = fmaxf(red[tid], red[tid + st]);
        __syncthreads();
    }
    m = red[0]; __syncthreads();
    float sum = 0.f;
    for (int i = tid; i < n; i += 256) {
        float p = __expf(row[i] * 0.125f - m);
        row[i] = p;
        sum += p;
    }
    red[tid] = sum; __syncthreads();
    for (int st = 128; st > 0; st >>= 1) {
        if (tid < st) red[tid] += red[tid + st];
        __syncthreads();
    }
    float inv = 1.f / red[0];
    for (int i = tid; i < n; i += 256) row[i] *= inv;
    for (int i = n + tid; i < SEQ; i += 256) row[i] = 0.f;
}

// ---------------- gate softmax + top-8 ----------------
__global__ void topk_kernel() {
    int t = blockIdx.x;
    int tid = threadIdx.x;
    __shared__ float gate[NEXP];
    __shared__ float red[NEXP];
    float lg = g_logits[t * NEXP + tid];
    red[tid] = lg; __syncthreads();
    for (int st = 32; st > 0; st >>= 1) {
        if (tid < st) red[tid] = fmaxf(red[tid], red[tid + st]);
        __syncthreads();
    }
    float m = red[0]; __syncthreads();
    float e = __expf(lg - m);
    gate[tid] = e;
    red[tid] = e; __syncthreads();
    for (int st = 32; st > 0; st >>= 1) {
        if (tid < st) red[tid] += red[tid + st];
        __syncthreads();
    }
    float inv = 1.f / red[0];
    __syncthreads();
    gate[tid] = e * inv;
    __syncthreads();
    if (tid == 0) {
        float vals[TOPK];
        int idxs[TOPK];
        float den = 0.f;
        for (int k = 0; k < TOPK; k++) {
            float bv = -INFINITY; int bi = 0;
            for (int i = 0; i < NEXP; i++) {
                float v = gate[i];
                if (v > bv) { bv = v; bi = i; }
            }
            vals[k] = bv; idxs[k] = bi; den += bv;
            gate[bi] = -INFINITY;
        }
        den = fmaxf(den, 1.19209290e-07f);
        for (int k = 0; k < TOPK; k++) {
            g_assign_e[t * TOPK + k] = idxs[k];
            g_assign_w[t * TOPK + k] = vals[k] / den;
        }
    }
}

// ---------------- routing ----------------
__global__ void route_kernel() {
    int e = threadIdx.x;
    int cnt = 0;
    for (int i = 0; i < SEQ * TOPK; i++) {
        if (g_assign_e[i] == e) {
            g_assign_p[i] = cnt;
            if (cnt < CAP) g_slot_token[e * CAP + cnt] = i >> 3;
            cnt++;
        }
    }
    g_count[e] = cnt < CAP ? cnt : CAP;
}

// ---------------- final combine ----------------
__global__ void combine_kernel(float* __restrict__ out) {
    int t = blockIdx.x;
    int tid = threadIdx.x;
    __shared__ float w[TOPK];
    __shared__ int rr[TOPK];
    if (tid < TOPK) {
        int i = t * TOPK + tid;
        int p = g_assign_p[i];
        int e = g_assign_e[i];
        bool valid = p < CAP;
        w[tid] = valid ? g_assign_w[i] : 0.f;
        rr[tid] = e * CAP + (valid ? p : 0);
    }
    __syncthreads();
    for (int h = tid; h < HDIM; h += 256) {
        float v = g_h1[(size_t)t * HDIM + h] + g_sharedo[(size_t)t * HDIM + h];
#pragma unroll
        for (int k = 0; k < TOPK; k++) v += w[k] * g_ye[(size_t)rr[k] * HDIM + h];
        out[(size_t)t * HDIM + h] = v;
    }
}

// ---------------- launch ----------------
extern "C" void kernel_launch(void* const* d_in, const int* in_sizes, int n_in,
                              void* d_out, int out_size) {
    const float* hidden = (const float*)d_in[0];
    const float* cosb = (const float*)d_in[1];
    const float* sinb = (const float*)d_in[2];
    const float* ln1_w = (const float*)d_in[3];
    const float* ln2_w = (const float*)d_in[4];
    const float* Wqkv = (const float*)d_in[5];
    const float* Wo = (const float*)d_in[6];
    const float* qnorm_w = (const float*)d_in[7];
    const float* knorm_w = (const float*)d_in[8];
    const float* Wgu_sh = (const float*)d_in[9];
    const float* Wd_sh = (const float*)d_in[10];
    const float* Wgate = (const float*)d_in[11];
    const float* Wgu_ex = (const float*)d_in[12];
    const float* Wd_ex = (const float*)d_in[13];
    float* out = (float*)d_out;

    float *pqkv, *pq, *pkT, *pv, *pscores, *pattn, *ph1, *px2, *psh, *plog, *pye;
    __half *pxh, *pxl, *px2h, *px2l, *phsh, *pheh;
    __half *pwgsh, *pwdsh, *pwgex, *pwdex;
    cudaGetSymbolAddress((void**)&pxh, g_x_h);
    cudaGetSymbolAddress((void**)&pxl, g_x_l);
    cudaGetSymbolAddress((void**)&pqkv, g_qkv);
    cudaGetSymbolAddress((void**)&pq, g_q);
    cudaGetSymbolAddress((void**)&pkT, g_kT);
    cudaGetSymbolAddress((void**)&pv, g_v);
    cudaGetSymbolAddress((void**)&pscores, g_scores);
    cudaGetSymbolAddress((void**)&pattn, g_attn);
    cudaGetSymbolAddress((void**)&ph1, g_h1);
    cudaGetSymbolAddress((void**)&px2, g_x2);
    cudaGetSymbolAddress((void**)&px2h, g_x2_h);
    cudaGetSymbolAddress((void**)&px2l, g_x2_l);
    cudaGetSymbolAddress((void**)&phsh, g_hs_h);
    cudaGetSymbolAddress((void**)&psh, g_sharedo);
    cudaGetSymbolAddress((void**)&plog, g_logits);
    cudaGetSymbolAddress((void**)&pheh, g_hexp_h);
    cudaGetSymbolAddress((void**)&pye, g_ye);
    cudaGetSymbolAddress((void**)&pwgsh, g_wgu_sh_h);
    cudaGetSymbolAddress((void**)&pwdsh, g_wd_sh_h);
    cudaGetSymbolAddress((void**)&pwgex, g_wgu_ex_h);
    cudaGetSymbolAddress((void**)&pwdex, g_wd_ex_h);

    static int attr_done = 0;
    if (!attr_done) {
        cudaFuncSetAttribute(hf_gemm3<false, true>, cudaFuncAttributeMaxDynamicSharedMemorySize, SM3_BYTES);
        cudaFuncSetAttribute(hf_gemm3<true, false>, cudaFuncAttributeMaxDynamicSharedMemorySize, SM3_BYTES);
        cudaFuncSetAttribute(hf_gemm1b<0, true>, cudaFuncAttributeMaxDynamicSharedMemorySize, SMP_BYTES);
        cudaFuncSetAttribute(hf_gemm1b<0, false>, cudaFuncAttributeMaxDynamicSharedMemorySize, SMP_BYTES);
        cudaFuncSetAttribute(hf_gemm1b<1, true>, cudaFuncAttributeMaxDynamicSharedMemorySize, SMP_BYTES);
        cudaFuncSetAttribute(hf_gemm1b<2, false>, cudaFuncAttributeMaxDynamicSharedMemorySize, SMP_BYTES);
        attr_done = 1;
    }

    // 0. weight conversions
    {
        long tot_i_sh = (long)HDIM * (IDIM / 4);
        conv_inter_kernel<<<(unsigned)((tot_i_sh + 255) / 256), 256>>>(Wgu_sh, pwgsh, IDIM / 4, tot_i_sh);
        long tot_i_ex = (long)NEXP * HDIM * (IDIM / 4);
        conv_inter_kernel<<<(unsigned)((tot_i_ex + 255) / 256), 256>>>(Wgu_ex, pwgex, IDIM / 4, tot_i_ex);
        long tot_p_sh = (long)IDIM * HDIM / 8;
        conv_plain_kernel<<<(unsigned)((tot_p_sh + 255) / 256), 256>>>(Wd_sh, pwdsh, tot_p_sh);
        long tot_p_ex = (long)NEXP * IDIM * HDIM / 8;
        conv_plain_kernel<<<(unsigned)((tot_p_ex + 255) / 256), 256>>>(Wd_ex, pwdex, tot_p_ex);
    }

    // 1. x = rmsnorm(hidden, ln1)
    rmsnorm_kernel<false><<<SEQ, 256>>>(hidden, ln1_w, nullptr, pxh, pxl);
    // 2. qkv = x @ Wqkv (3-pass)
    hf_gemm3<false, true><<<dim3(16, 8), 256, SM3_BYTES>>>(
        pxh, pxl, Wqkv, pqkv, nullptr, 2048, 1024);
    // 3. rope + qknorm + split
    rope_qk_kernel<<<dim3(SEQ, KVHEADS), 128>>>(cosb, sinb, qnorm_w, knorm_w);
    // 4. scores = q @ k^T (causal block-skip)
    sgemm_kernel<false, 1><<<dim3(8, 8, NHEADS), 256>>>(pq, pkT, pscores, nullptr,
        1024, 1024, 64, 64, 1024, 1024, 65536, 65536, 1048576, 2);
    // 5. causal softmax
    softmax_kernel<<<dim3(SEQ, NHEADS), 256>>>();
    // 6. attn = P @ V (K capped per row-block)
    sgemm_kernel<false, 2><<<dim3(1, 8, NHEADS), 256>>>(pscores, pv, pattn, nullptr,
        1024, 64, 1024, 1024, 64, 1024, 1048576, 65536, 64, 2);
    // 7. h1 = attn @ Wo + hidden (3-pass)
    hf_gemm3<true, false><<<dim3(8, 8), 256, SM3_BYTES>>>(
        pattn, nullptr, Wo, ph1, hidden, 1024, 1024);
    // 8. x2 = rmsnorm(h1, ln2)
    rmsnorm_kernel<true><<<SEQ, 256>>>(ph1, ln2_w, px2, px2h, px2l);
    // 9+10. hs = swiglu(x2 @ Wgu_shared)
    hf_gemm1b<0, true><<<dim3(48, 8), 256, SMP_BYTES>>>(px2h, pwgsh, nullptr, phsh, 6144, 1024);
    // 11. shared = hs @ Wd_shared
    hf_gemm1b<0, false><<<dim3(8, 8), 256, SMP_BYTES>>>(phsh, pwdsh, psh, nullptr, 1024, 3072);
    // 12. logits = x2 @ Wgate (fp32)
    sgemm_kernel<false, 0><<<dim3(1, 8, 1), 256>>>(px2, Wgate, plog, nullptr,
        1024, 64, 1024, 1024, 64, 64, 0, 0, 0, 1);
    // 13. softmax + top8
    topk_kernel<<<SEQ, 64>>>();
    // 14. routing
    route_kernel<<<1, 64>>>();
    // 15+16. hexp = swiglu(gather(x2) @ Wgu_experts)
    hf_gemm1b<1, true><<<dim3(48, 256), 256, SMP_BYTES>>>(px2h, pwgex, nullptr, pheh, 6144, 1024);
    // 17. ye = hexp @ Wd_experts
    hf_gemm1b<2, false><<<dim3(8, 256), 256, SMP_BYTES>>>(pheh, pwdex, pye, nullptr, 1024, 3072);
    // 18. out = h1 + shared + moe
    combine_kernel<<<SEQ, 256>>>(out);
}

// round 17
// speedup vs baseline: 1.1135x; 1.0220x over previous
#include <cuda_runtime.h>
#include <cuda_fp16.h>
#include <math.h>
#include <stdint.h>

#define SEQ 1024
#define HDIM 1024
#define NHEADS 16
#define KVHEADS 8
#define HSZ 64
#define NEXP 64
#define TOPK 8
#define CAP 512
#define IDIM 3072
#define EPSF 1e-6f

// ---------------- scratch ----------------
__device__ __half g_x_h[SEQ * HDIM];
__device__ __half g_x_l[SEQ * HDIM];
__device__ float g_qkv[SEQ * 2048];
__device__ float g_q[NHEADS * SEQ * HSZ];
__device__ float g_kT[KVHEADS * HSZ * SEQ];
__device__ float g_v[KVHEADS * SEQ * HSZ];
__device__ float g_scores[(size_t)NHEADS * SEQ * SEQ];
__device__ float g_attn[SEQ * HDIM];
__device__ float g_h1[SEQ * HDIM];
__device__ float g_x2[SEQ * HDIM];
__device__ __half g_x2_h[SEQ * HDIM];
__device__ __half g_x2_l[SEQ * HDIM];
__device__ __half g_hs_h[SEQ * IDIM];
__device__ float g_sharedo[SEQ * HDIM];
__device__ float g_logits[SEQ * NEXP];
__device__ int   g_assign_e[SEQ * TOPK];
__device__ float g_assign_w[SEQ * TOPK];
__device__ int   g_assign_p[SEQ * TOPK];
__device__ int   g_slot_token[NEXP * CAP];
__device__ int   g_count[NEXP];
__device__ __half g_hexp_h[(size_t)NEXP * CAP * IDIM];
__device__ float g_ye[(size_t)NEXP * CAP * HDIM];
// pre-converted fp16 weights
__device__ __half g_wgu_sh_h[(size_t)HDIM * 2 * IDIM];
__device__ __half g_wd_sh_h[(size_t)IDIM * HDIM];
__device__ __half g_wgu_ex_h[(size_t)NEXP * HDIM * 2 * IDIM];
__device__ __half g_wd_ex_h[(size_t)NEXP * IDIM * HDIM];

// ---------------- helpers ----------------
__device__ __forceinline__ uint32_t smem_u32(const void* p) {
    uint32_t a;
    asm("{ .reg .u64 t; cvta.to.shared.u64 t, %1; cvt.u32.u64 %0, t; }" : "=r"(a) : "l"(p));
    return a;
}
__device__ __forceinline__ uint32_t pack_h2(float a, float b) {
    __half2 t = __floats2half2_rn(a, b);
    return *reinterpret_cast<uint32_t*>(&t);
}
__device__ __forceinline__ void splitw_h(float v, __half& h, __half& l) {
    __half hh = __float2half_rn(v);
    h = hh;
    l = __float2half_rn(v - __half2float(hh));
}
__device__ __forceinline__ void split4h(float4 v, uint2& h, uint2& l) {
    __half2 h0 = __floats2half2_rn(v.x, v.y);
    __half2 h1 = __floats2half2_rn(v.z, v.w);
    float2 f0 = __half22float2(h0);
    float2 f1 = __half22float2(h1);
    __half2 l0 = __floats2half2_rn(v.x - f0.x, v.y - f0.y);
    __half2 l1 = __floats2half2_rn(v.z - f1.x, v.w - f1.y);
    h.x = *reinterpret_cast<uint32_t*>(&h0);
    h.y = *reinterpret_cast<uint32_t*>(&h1);
    l.x = *reinterpret_cast<uint32_t*>(&l0);
    l.y = *reinterpret_cast<uint32_t*>(&l1);
}
__device__ __forceinline__ void ldmx4(uint32_t* r, uint32_t addr) {
    asm volatile("ldmatrix.sync.aligned.m8n8.x4.shared.b16 {%0,%1,%2,%3}, [%4];"
                 : "=r"(r[0]), "=r"(r[1]), "=r"(r[2]), "=r"(r[3]) : "r"(addr));
}
__device__ __forceinline__ void ldmx2t(uint32_t* r, uint32_t addr) {
    asm volatile("ldmatrix.sync.aligned.m8n8.x2.trans.shared.b16 {%0,%1}, [%2];"
                 : "=r"(r[0]), "=r"(r[1]) : "r"(addr));
}
__device__ __forceinline__ void mma_h(float* d, const uint32_t* a, const uint32_t* b) {
    asm volatile("mma.sync.aligned.m16n8k16.row.col.f32.f16.f16.f32 "
                 "{%0,%1,%2,%3}, {%4,%5,%6,%7}, {%8,%9}, {%0,%1,%2,%3};"
                 : "+f"(d[0]), "+f"(d[1]), "+f"(d[2]), "+f"(d[3])
                 : "r"(a[0]), "r"(a[1]), "r"(a[2]), "r"(a[3]), "r"(b[0]), "r"(b[1]));
}
__device__ __forceinline__ void cpasync16(uint32_t saddr, const void* g) {
    asm volatile("cp.async.ca.shared.global [%0], [%1], 16;" :: "r"(saddr), "l"(g) : "memory");
}
#define CPCOMMIT() asm volatile("cp.async.commit_group;" ::: "memory")
#define CPWAIT(n)  asm volatile("cp.async.wait_group %0;" :: "n"(n) : "memory")

// ---------------- weight conversion kernels ----------------
__global__ void conv_inter_kernel(const float* __restrict__ in, __half* __restrict__ out,
                                  int I2, long total) {
    long idx = (long)blockIdx.x * 256 + threadIdx.x;
    if (idx >= total) return;
    long k = idx / I2;
    int j4 = (int)(idx % I2) * 4;
    const float* row = in + k * (size_t)(2 * I2 * 4);
    float4 va = *(const float4*)(row + j4);
    float4 vb = *(const float4*)(row + I2 * 4 + j4);
    uint4 o;
    o.x = pack_h2(va.x, vb.x);
    o.y = pack_h2(va.y, vb.y);
    o.z = pack_h2(va.z, vb.z);
    o.w = pack_h2(va.w, vb.w);
    *(uint4*)(out + k * (size_t)(2 * I2 * 4) + 2 * j4) = o;
}
__global__ void conv_plain_kernel(const float* __restrict__ in, __half* __restrict__ out,
                                  long total8) {
    long idx = (long)blockIdx.x * 256 + threadIdx.x;
    if (idx >= total8) return;
    const float4 v0 = *(const float4*)(in + idx * 8);
    const float4 v1 = *(const float4*)(in + idx * 8 + 4);
    uint4 o;
    o.x = pack_h2(v0.x, v0.y);
    o.y = pack_h2(v0.z, v0.w);
    o.z = pack_h2(v1.x, v1.y);
    o.w = pack_h2(v1.z, v1.w);
    *(uint4*)(out + idx * 8) = o;
}

// ======== 1-pass fp16 GEMM, fp16 weights, full cp.async, 3-stage, 2 CTAs/SM ========
#define APAD 40
#define BPAD 136
#define A_EL (128 * APAD)
#define B_EL (32 * BPAD)
#define SMP_BYTES (3 * (A_EL + B_EL) * 2)

template <int MODE, bool FUSE>
__global__ void __launch_bounds__(256, 2) hf_gemm1b(const __half* __restrict__ A,
                                                    const __half* __restrict__ Bh,
                                                    float* __restrict__ C,
                                                    __half* __restrict__ Oh,
                                                    int N, int K) {
    extern __shared__ __align__(16) __half sm[];
    int tid = threadIdx.x, lane = tid & 31, wid = tid >> 5;
    int wm = wid & 1, wn = wid >> 1;

    int e = 0, slot0 = 0, cnt = 128;
    size_t crow0;
    if (MODE == 0) {
        crow0 = (size_t)blockIdx.y * 128;
    } else {
        int t = blockIdx.y;
        e = t >> 2;
        slot0 = (t & 3) * 128;
        int c = g_count[e] - slot0;
        if (c <= 0) return;
        cnt = c < 128 ? c : 128;
        Bh += (size_t)e * K * N;
        crow0 = (size_t)e * CAP + slot0;
    }
    int n0 = blockIdx.x * 128;

    int a_row = tid >> 1;
    int a_q = (tid & 1) * 16;
    int b_row = tid >> 3;
    int b_q = (tid & 7) * 16;

    bool aok = a_row < cnt;
    size_t a_off;
    if (MODE == 1) {
        int tok = aok ? g_slot_token[e * CAP + slot0 + a_row] : 0;
        a_off = (size_t)tok * K + a_q;
    } else {
        a_off = (crow0 + a_row) * (size_t)K + a_q;
    }
    const __half* aptr = A + a_off;
    const __half* bptr = Bh + (size_t)b_row * N + n0 + b_q;

    float acc[4][4][4];
#pragma unroll
    for (int i = 0; i < 4; i++)
#pragma unroll
        for (int j = 0; j < 4; j++)
#pragma unroll
            for (int v = 0; v < 4; v++) acc[i][j][v] = 0.f;

    uint32_t sbase = smem_u32(sm);
    int oa = a_row * APAD + a_q;
    int ob = b_row * BPAD + b_q;

    if (MODE != 0 && !aok) {
        uint4 z = make_uint4(0, 0, 0, 0);
#pragma unroll
        for (int s = 0; s < 3; s++) {
            *(uint4*)(sm + s * A_EL + oa) = z;
            *(uint4*)(sm + s * A_EL + oa + 8) = z;
        }
    }

    auto issue = [&](int s, int k0) {
        if (aok) {
            uint32_t da = sbase + (s * A_EL + oa) * 2;
            cpasync16(da, aptr + k0);
            cpasync16(da + 16, aptr + k0 + 8);
        }
        uint32_t db = sbase + (3 * A_EL + s * B_EL + ob) * 2;
        cpasync16(db, bptr + (size_t)k0 * N);
        cpasync16(db + 16, bptr + (size_t)k0 * N + 8);
        CPCOMMIT();
    };

    int nk = K >> 5;
    issue(0, 0);
    if (nk > 1) { issue(1, 32); CPWAIT(1); }
    else CPWAIT(0);
    __syncthreads();

    for (int c = 0; c < nk; c++) {
        int s = c % 3;
        if (c + 2 < nk) issue((c + 2) % 3, (c + 2) << 5);

        uint32_t ao = sbase + (s * A_EL) * 2;
        uint32_t bo = sbase + (3 * A_EL + s * B_EL) * 2;
#pragma unroll
        for (int ks = 0; ks < 2; ks++) {
            uint32_t ah[4][4], bh[4][2];
#pragma unroll
            for (int i = 0; i < 4; i++) {
                uint32_t off = ((wm * 64 + i * 16 + (lane & 15)) * APAD + ks * 16 + (lane >> 4) * 8) * 2;
                ldmx4(ah[i], ao + off);
            }
#pragma unroll
            for (int j = 0; j < 4; j++) {
                uint32_t off = ((ks * 16 + (lane & 15)) * BPAD + wn * 32 + j * 8) * 2;
                ldmx2t(bh[j], bo + off);
            }
#pragma unroll
            for (int i = 0; i < 4; i++)
#pragma unroll
                for (int j = 0; j < 4; j++) mma_h(acc[i][j], ah[i], bh[j]);
        }

        if (c + 1 < nk) {
            if (c + 2 < nk) CPWAIT(1);
            else CPWAIT(0);
        }
        __syncthreads();
    }

    // ---- epilogue ----
    if (FUSE) {
        int NP = N >> 1;
#pragma unroll
        for (int i = 0; i < 4; i++) {
            int r0 = wm * 64 + i * 16 + (lane >> 2);
#pragma unroll
            for (int j = 0; j < 4; j++) {
                int c0 = n0 + wn * 32 + j * 8 + (lane & 3) * 2;
                int p = c0 >> 1;
                {
                    float a = acc[i][j][0], b = acc[i][j][1];
                    float h = a * (b / (1.f + __expf(-b)));
                    Oh[(crow0 + r0) * (size_t)NP + p] = __float2half_rn(h);
                }
                {
                    float a = acc[i][j][2], b = acc[i][j][3];
                    float h = a * (b / (1.f + __expf(-b)));
                    Oh[(crow0 + r0 + 8) * (size_t)NP + p] = __float2half_rn(h);
                }
            }
        }
    } else {
#pragma unroll
        for (int i = 0; i < 4; i++) {
            int r0 = wm * 64 + i * 16 + (lane >> 2);
#pragma unroll
            for (int j = 0; j < 4; j++) {
                int c0 = n0 + wn * 32 + j * 8 + (lane & 3) * 2;
                float* cp = C + (crow0 + r0) * (size_t)N + c0;
                float* cp2 = C + (crow0 + r0 + 8) * (size_t)N + c0;
                cp[0] = acc[i][j][0];
                cp[1] = acc[i][j][1];
                cp2[0] = acc[i][j][2];
                cp2[1] = acc[i][j][3];
            }
        }
    }
}

// ======== 3-pass fp16 split GEMM, BK=32 (qkv / Wo precision path) ========
#define OFF_AH(b) ((b) * A_EL)
#define OFF_AL(b) (2 * A_EL + (b) * A_EL)
#define OFF_B(b)  (4 * A_EL + (b) * B_EL)
#define OFF_BL(b) (4 * A_EL + 2 * B_EL + (b) * B_EL)
#define SM3_BYTES ((4 * A_EL + 4 * B_EL) * 2)

template <bool RES, bool ASPLIT>
__global__ void __launch_bounds__(256, 1) hf_gemm3(const void* __restrict__ Av,
                                                   const __half* __restrict__ Alp,
                                                   const float* __restrict__ B,
                                                   float* __restrict__ C,
                                                   const float* __restrict__ res,
                                                   int N, int K) {
    extern __shared__ __align__(16) __half sm[];
    int tid = threadIdx.x, lane = tid & 31, wid = tid >> 5;
    int wm = wid & 1, wn = wid >> 1;
    size_t crow0 = (size_t)blockIdx.y * 128;
    int n0 = blockIdx.x * 128;

    int a_row = tid >> 1;
    int a_q = (tid & 1) * 16;
    int b_row = tid >> 3;
    int b_q = (tid & 7) * 16;

    size_t a_off = (crow0 + a_row) * (size_t)K + a_q;
    const float* aptr_f = (const float*)Av + a_off;
    const __half* aptr_h = (const __half*)Av + a_off;
    const __half* aptr_l = Alp + a_off;
    const float* bptr = B + (size_t)b_row * N + n0 + b_q;

    float acc[4][4][4];
#pragma unroll
    for (int i = 0; i < 4; i++)
#pragma unroll
        for (int j = 0; j < 4; j++)
#pragma unroll
            for (int v = 0; v < 4; v++) acc[i][j][v] = 0.f;

    uint32_t sbase = smem_u32(sm);
    int oa = a_row * APAD + a_q;
    uint32_t aAH0 = sbase + (OFF_AH(0) + oa) * 2;
    uint32_t aAH1 = sbase + (OFF_AH(1) + oa) * 2;
    uint32_t aAL0 = sbase + (OFF_AL(0) + oa) * 2;
    uint32_t aAL1 = sbase + (OFF_AL(1) + oa) * 2;

    auto issue_a = [&](int buf, int k0) {
        if (ASPLIT) {
            uint32_t dh = buf ? aAH1 : aAH0;
            cpasync16(dh, aptr_h + k0);
            cpasync16(dh + 16, aptr_h + k0 + 8);
            uint32_t dl = buf ? aAL1 : aAL0;
            cpasync16(dl, aptr_l + k0);
            cpasync16(dl + 16, aptr_l + k0 + 8);
            CPCOMMIT();
        }
    };

    float4 pa[4];
    float4 pb[4];
    auto load_b = [&](int k0) {
        size_t krow = (size_t)k0 * N;
#pragma unroll
        for (int j = 0; j < 4; j++) pb[j] = *(const float4*)(bptr + krow + j * 4);
    };
    auto store_stage = [&](int buf) {
        if (!ASPLIT) {
            __half* AH = sm + OFF_AH(buf);
            __half* AL = sm + OFF_AL(buf);
#pragma unroll
            for (int j = 0; j < 4; j++) {
                uint2 h, l;
                split4h(pa[j], h, l);
                *(uint2*)(AH + oa + j * 4) = h;
                *(uint2*)(AL + oa + j * 4) = l;
            }
        }
        __half* BP = sm + OFF_B(buf);
        __half* BL = sm + OFF_BL(buf);
        int ob = b_row * BPAD + b_q;
#pragma unroll
        for (int j = 0; j < 4; j++) {
            uint2 h, l;
            split4h(pb[j], h, l);
            *(uint2*)(BP + ob + j * 4) = h;
            *(uint2*)(BL + ob + j * 4) = l;
        }
    };

    issue_a(0, 0);
    if (!ASPLIT) {
#pragma unroll
        for (int j = 0; j < 4; j++) pa[j] = *(const float4*)(aptr_f + j * 4);
    }
    load_b(0);
    store_stage(0);
    if (ASPLIT) CPWAIT(0);
    __syncthreads();

    int nk = K >> 5;
    for (int c = 0; c < nk; c++) {
        int cur = c & 1;
        bool more = (c + 1) < nk;
        if (more) {
            int k1 = (c + 1) << 5;
            issue_a(cur ^ 1, k1);
            if (!ASPLIT) {
#pragma unroll
                for (int j = 0; j < 4; j++) pa[j] = *(const float4*)(aptr_f + k1 + j * 4);
            }
            load_b(k1);
        }

        uint32_t aho = sbase + OFF_AH(cur) * 2;
        uint32_t alo = sbase + OFF_AL(cur) * 2;
        uint32_t bo = sbase + OFF_B(cur) * 2;
        uint32_t blo = sbase + OFF_BL(cur) * 2;
#pragma unroll
        for (int ks = 0; ks < 2; ks++) {
            uint32_t ah[4][4], al[4][4], bh[4][2], bl[4][2];
#pragma unroll
            for (int i = 0; i < 4; i++) {
                uint32_t off = ((wm * 64 + i * 16 + (lane & 15)) * APAD + ks * 16 + (lane >> 4) * 8) * 2;
                ldmx4(ah[i], aho + off);
                ldmx4(al[i], alo + off);
            }
#pragma unroll
            for (int j = 0; j < 4; j++) {
                uint32_t off = ((ks * 16 + (lane & 15)) * BPAD + wn * 32 + j * 8) * 2;
                ldmx2t(bh[j], bo + off);
                ldmx2t(bl[j], blo + off);
            }
#pragma unroll
            for (int i = 0; i < 4; i++)
#pragma unroll
                for (int j = 0; j < 4; j++) mma_h(acc[i][j], ah[i], bh[j]);
#pragma unroll
            for (int i = 0; i < 4; i++)
#pragma unroll
                for (int j = 0; j < 4; j++) mma_h(acc[i][j], al[i], bh[j]);
#pragma unroll
            for (int i = 0; i < 4; i++)
#pragma unroll
                for (int j = 0; j < 4; j++) mma_h(acc[i][j], ah[i], bl[j]);
        }

        if (more) store_stage(cur ^ 1);
        if (ASPLIT && more) CPWAIT(0);
        __syncthreads();
    }

#pragma unroll
    for (int i = 0; i < 4; i++) {
        int r0 = wm * 64 + i * 16 + (lane >> 2);
#pragma unroll
        for (int j = 0; j < 4; j++) {
            int c0 = n0 + wn * 32 + j * 8 + (lane & 3) * 2;
            float* cp = C + (crow0 + r0) * (size_t)N + c0;
            float* cp2 = C + (crow0 + r0 + 8) * (size_t)N + c0;
            if (RES) {
                const float* rp = res + (crow0 + r0) * (size_t)N + c0;
                const float* rp2 = res + (crow0 + r0 + 8) * (size_t)N + c0;
                cp[0] = acc[i][j][0] + rp[0];
                cp[1] = acc[i][j][1] + rp[1];
                cp2[0] = acc[i][j][2] + rp2[0];
                cp2[1] = acc[i][j][3] + rp2[1];
            } else {
                cp[0] = acc[i][j][0];
                cp[1] = acc[i][j][1];
                cp2[0] = acc[i][j][2];
                cp2[1] = acc[i][j][3];
            }
        }
    }
}

// ---------------- rmsnorm ----------------
template <bool OUT32>
__global__ void rmsnorm_kernel(const float* __restrict__ in, const float* __restrict__ w,
                               float* __restrict__ out32,
                               __half* __restrict__ oh, __half* __restrict__ ol) {
    int row = blockIdx.x;
    const float* x = in + (size_t)row * HDIM;
    __shared__ float red[256];
    float s = 0.f;
    for (int i = threadIdx.x; i < HDIM; i += 256) { float v = x[i]; s += v * v; }
    red[threadIdx.x] = s; __syncthreads();
    for (int st = 128; st > 0; st >>= 1) {
        if (threadIdx.x < st) red[threadIdx.x] += red[threadIdx.x + st];
        __syncthreads();
    }
    float inv = rsqrtf(red[0] / (float)HDIM + EPSF);
    for (int i = threadIdx.x; i < HDIM; i += 256) {
        float v = w[i] * x[i] * inv;
        if (OUT32) out32[(size_t)row * HDIM + i] = v;
        __half h, l;
        splitw_h(v, h, l);
        oh[(size_t)row * HDIM + i] = h;
        ol[(size_t)row * HDIM + i] = l;
    }
}

// ---------------- fp32 SGEMM (attention + logits) ----------------
template <bool RES, int KM>
__global__ void sgemm_kernel(const float* __restrict__ A, const float* __restrict__ B,
                             float* __restrict__ C, const float* __restrict__ res,
                             int M, int N, int K, int lda, int ldb, int ldc,
                             long sA, long sB, long sC, int bdiv) {
    int z = blockIdx.z;
    int row0 = blockIdx.y * 128, col0 = blockIdx.x * 128;
    if (KM == 1 && col0 > row0) return;
    int Keff = K;
    if (KM == 2) Keff = (row0 + 128 < K) ? row0 + 128 : K;
    A += (size_t)z * sA;
    B += (size_t)(z / bdiv) * sB;
    C += (size_t)z * sC;
    if (RES) res += (size_t)z * sC;
    __shared__ float As[8][128];
    __shared__ float Bs[8][128];
    int tid = threadIdx.x;
    int tx = tid & 15, ty = tid >> 4;
    int arow = tid >> 1;
    int acol = (tid & 1) * 4;
    int brow = tid >> 5;
    int bcol = (tid & 31) * 4;
    const float* Aptr = A + (size_t)(row0 + arow) * lda + acol;
    const float* Bptr = B + (size_t)brow * ldb + col0 + bcol;
    bool bok = (col0 + bcol) < N;
    float acc[8][8];
#pragma unroll
    for (int i = 0; i < 8; i++)
#pragma unroll
        for (int j = 0; j < 8; j++) acc[i][j] = 0.f;

    for (int k0 = 0; k0 < Keff; k0 += 8) {
        float4 av = *(const float4*)(Aptr + k0);
        As[acol + 0][arow] = av.x;
        As[acol + 1][arow] = av.y;
        As[acol + 2][arow] = av.z;
        As[acol + 3][arow] = av.w;
        float4 bv = make_float4(0.f, 0.f, 0.f, 0.f);
        if (bok) bv = *(const float4*)(Bptr + (size_t)k0 * ldb);
        *(float4*)&Bs[brow][bcol] = bv;
        __syncthreads();
#pragma unroll
        for (int kk = 0; kk < 8; kk++) {
            float am[8], bn[8];
#pragma unroll
            for (int i = 0; i < 8; i++) am[i] = As[kk][ty * 8 + i];
#pragma unroll
            for (int j = 0; j < 8; j++) bn[j] = Bs[kk][tx * 8 + j];
#pragma unroll
            for (int i = 0; i < 8; i++)
#pragma unroll
                for (int j = 0; j < 8; j++) acc[i][j] += am[i] * bn[j];
        }
        __syncthreads();
    }
#pragma unroll
    for (int i = 0; i < 8; i++) {
        int r = row0 + ty * 8 + i;
#pragma unroll
        for (int j = 0; j < 8; j++) {
            int c = col0 + tx * 8 + j;
            if (c < N) {
                float v = acc[i][j];
                if (RES) v += res[(size_t)r * ldc + c];
                C[(size_t)r * ldc + c] = v;
            }
        }
    }
}

// ---------------- RoPE + qk rmsnorm + layout split ----------------
__global__ void rope_qk_kernel(const float* __restrict__ cosb, const float* __restrict__ sinb,
                               const float* __restrict__ qw, const float* __restrict__ kw) {
    int s = blockIdx.x, kv = blockIdx.y;
    int w = threadIdx.x >> 5, lane = threadIdx.x & 31;
    const float* src = g_qkv + (size_t)s * 2048 + kv * 256 + w * 64;
    float x1 = src[lane], x2 = src[lane + 32];
    float o1, o2;
    if (w < 3) {
        float c1 = cosb[s * 64 + lane], s1 = sinb[s * 64 + lane];
        float c2 = cosb[s * 64 + lane + 32], s2 = sinb[s * 64 + lane + 32];
        o1 = x1 * c1 - x2 * s1;
        o2 = x2 * c2 + x1 * s2;
        float ss = o1 * o1 + o2 * o2;
#pragma unroll
        for (int off = 16; off; off >>= 1) ss += __shfl_xor_sync(0xffffffffu, ss, off);
        float inv = rsqrtf(ss / 64.f + EPSF);
        const float* wt = (w < 2) ? qw : kw;
        o1 *= inv * wt[lane];
        o2 *= inv * wt[lane + 32];
    } else {
        o1 = x1; o2 = x2;
    }
    if (w < 2) {
        int head = kv * 2 + w;
        g_q[(size_t)head * 65536 + s * 64 + lane] = o1;
        g_q[(size_t)head * 65536 + s * 64 + lane + 32] = o2;
    } else if (w == 2) {
        g_kT[(size_t)kv * 65536 + lane * 1024 + s] = o1;
        g_kT[(size_t)kv * 65536 + (lane + 32) * 1024 + s] = o2;
    } else {
        g_v[(size_t)kv * 65536 + s * 64 + lane] = o1;
        g_v[(size_t)kv * 65536 + s * 64 + lane + 32] = o2;
    }
}

// ---------------- causal scaled softmax ----------------
__global__ void softmax_kernel() {
    int s = blockIdx.x, h = blockIdx.y;
    float* row = g_scores + ((size_t)h * SEQ + s) * SEQ;
    int n = s + 1;
    __shared__ float red[256];
    int tid = threadIdx.x;
    float m = -INFINITY;
    for (int i = tid; i < n; i += 256) m = fmaxf(m, row[i] * 0.125f);
    red[tid] = m; __syncthreads();
    for (int st = 128; st > 0; st >>= 1) {
        if (tid < st) red[tid] = fmaxf(red[tid], red[tid + st]);
        __syncthreads();
    }
    m = red[0]; __syncthreads();
    float sum = 0.f;
    for (int i = tid; i < n; i += 256) {
        float p = __expf(row[i] * 0.125f - m);
        row[i] = p;
        sum += p;
    }
    red[tid] = sum; __syncthreads();
    for (int st = 128; st > 0; st >>= 1) {
        if (tid < st) red[tid] += red[tid + st];
        __syncthreads();
    }
    float inv = 1.f / red[0];
    for (int i = tid; i < n; i += 256) row[i] *= inv;
    for (int i = n + tid; i < SEQ; i += 256) row[i] = 0.f;
}

// ---------------- gate softmax + top-8 ----------------
__global__ void topk_kernel() {
    int t = blockIdx.x;
    int tid = threadIdx.x;
    __shared__ float gate[NEXP];
    __shared__ float red[NEXP];
    float lg = g_logits[t * NEXP + tid];
    red[tid] = lg; __syncthreads();
    for (int st = 32; st > 0; st >>= 1) {
        if (tid < st) red[tid] = fmaxf(red[tid], red[tid + st]);
        __syncthreads();
    }
    float m = red[0]; __syncthreads();
    float e = __expf(lg - m);
    gate[tid] = e;
    red[tid] = e; __syncthreads();
    for (int st = 32; st > 0; st >>= 1) {
        if (tid < st) red[tid] += red[tid + st];
        __syncthreads();
    }
    float inv = 1.f / red[0];
    __syncthreads();
    gate[tid] = e * inv;
    __syncthreads();
    if (tid == 0) {
        float vals[TOPK];
        int idxs[TOPK];
        float den = 0.f;
        for (int k = 0; k < TOPK; k++) {
            float bv = -INFINITY; int bi = 0;
            for (int i = 0; i < NEXP; i++) {
                float v = gate[i];
                if (v > bv) { bv = v; bi = i; }
            }
            vals[k] = bv; idxs[k] = bi; den += bv;
            gate[bi] = -INFINITY;
        }
        den = fmaxf(den, 1.19209290e-07f);
        for (int k = 0; k < TOPK; k++) {
            g_assign_e[t * TOPK + k] = idxs[k];
            g_assign_w[t * TOPK + k] = vals[k] / den;
        }
    }
}

// ---------------- routing ----------------
__global__ void route_kernel() {
    int e = threadIdx.x;
    int cnt = 0;
    for (int i = 0; i < SEQ * TOPK; i++) {
        if (g_assign_e[i] == e) {
            g_assign_p[i] = cnt;
            if (cnt < CAP) g_slot_token[e * CAP + cnt] = i >> 3;
            cnt++;
        }
    }
    g_count[e] = cnt < CAP ? cnt : CAP;
}

// ---------------- final combine ----------------
__global__ void combine_kernel(float* __restrict__ out) {
    int t = blockIdx.x;
    int tid = threadIdx.x;
    __shared__ float w[TOPK];
    __shared__ int rr[TOPK];
    if (tid < TOPK) {
        int i = t * TOPK + tid;
        int p = g_assign_p[i];
        int e = g_assign_e[i];
        bool valid = p < CAP;
        w[tid] = valid ? g_assign_w[i] : 0.f;
        rr[tid] = e * CAP + (valid ? p : 0);
    }
    __syncthreads();
    for (int h = tid; h < HDIM; h += 256) {
        float v = g_h1[(size_t)t * HDIM + h] + g_sharedo[(size_t)t * HDIM + h];
#pragma unroll
        for (int k = 0; k < TOPK; k++) v += w[k] * g_ye[(size_t)rr[k] * HDIM + h];
        out[(size_t)t * HDIM + h] = v;
    }
}

// ---------------- launch ----------------
extern "C" void kernel_launch(void* const* d_in, const int* in_sizes, int n_in,
                              void* d_out, int out_size) {
    const float* hidden = (const float*)d_in[0];
    const float* cosb = (const float*)d_in[1];
    const float* sinb = (const float*)d_in[2];
    const float* ln1_w = (const float*)d_in[3];
    const float* ln2_w = (const float*)d_in[4];
    const float* Wqkv = (const float*)d_in[5];
    const float* Wo = (const float*)d_in[6];
    const float* qnorm_w = (const float*)d_in[7];
    const float* knorm_w = (const float*)d_in[8];
    const float* Wgu_sh = (const float*)d_in[9];
    const float* Wd_sh = (const float*)d_in[10];
    const float* Wgate = (const float*)d_in[11];
    const float* Wgu_ex = (const float*)d_in[12];
    const float* Wd_ex = (const float*)d_in[13];
    float* out = (float*)d_out;

    float *pqkv, *pq, *pkT, *pv, *pscores, *pattn, *ph1, *px2, *psh, *plog, *pye;
    __half *pxh, *pxl, *px2h, *px2l, *phsh, *pheh;
    __half *pwgsh, *pwdsh, *pwgex, *pwdex;
    cudaGetSymbolAddress((void**)&pxh, g_x_h);
    cudaGetSymbolAddress((void**)&pxl, g_x_l);
    cudaGetSymbolAddress((void**)&pqkv, g_qkv);
    cudaGetSymbolAddress((void**)&pq, g_q);
    cudaGetSymbolAddress((void**)&pkT, g_kT);
    cudaGetSymbolAddress((void**)&pv, g_v);
    cudaGetSymbolAddress((void**)&pscores, g_scores);
    cudaGetSymbolAddress((void**)&pattn, g_attn);
    cudaGetSymbolAddress((void**)&ph1, g_h1);
    cudaGetSymbolAddress((void**)&px2, g_x2);
    cudaGetSymbolAddress((void**)&px2h, g_x2_h);
    cudaGetSymbolAddress((void**)&px2l, g_x2_l);
    cudaGetSymbolAddress((void**)&phsh, g_hs_h);
    cudaGetSymbolAddress((void**)&psh, g_sharedo);
    cudaGetSymbolAddress((void**)&plog, g_logits);
    cudaGetSymbolAddress((void**)&pheh, g_hexp_h);
    cudaGetSymbolAddress((void**)&pye, g_ye);
    cudaGetSymbolAddress((void**)&pwgsh, g_wgu_sh_h);
    cudaGetSymbolAddress((void**)&pwdsh, g_wd_sh_h);
    cudaGetSymbolAddress((void**)&pwgex, g_wgu_ex_h);
    cudaGetSymbolAddress((void**)&pwdex, g_wd_ex_h);

    static cudaStream_t s2 = nullptr;
    static cudaEvent_t ev_fork = nullptr, ev_join = nullptr;
    static int attr_done = 0;
    if (!attr_done) {
        cudaFuncSetAttribute(hf_gemm3<false, true>, cudaFuncAttributeMaxDynamicSharedMemorySize, SM3_BYTES);
        cudaFuncSetAttribute(hf_gemm3<true, false>, cudaFuncAttributeMaxDynamicSharedMemorySize, SM3_BYTES);
        cudaFuncSetAttribute(hf_gemm1b<0, true>, cudaFuncAttributeMaxDynamicSharedMemorySize, SMP_BYTES);
        cudaFuncSetAttribute(hf_gemm1b<0, false>, cudaFuncAttributeMaxDynamicSharedMemorySize, SMP_BYTES);
        cudaFuncSetAttribute(hf_gemm1b<1, true>, cudaFuncAttributeMaxDynamicSharedMemorySize, SMP_BYTES);
        cudaFuncSetAttribute(hf_gemm1b<2, false>, cudaFuncAttributeMaxDynamicSharedMemorySize, SMP_BYTES);
        cudaStreamCreateWithFlags(&s2, cudaStreamNonBlocking);
        cudaEventCreateWithFlags(&ev_fork, cudaEventDisableTiming);
        cudaEventCreateWithFlags(&ev_join, cudaEventDisableTiming);
        attr_done = 1;
    }

    // ---- fork: weight conversions on side stream, overlapped with attention ----
    cudaEventRecord(ev_fork, 0);
    cudaStreamWaitEvent(s2, ev_fork, 0);
    {
        long tot_i_sh = (long)HDIM * (IDIM / 4);
        conv_inter_kernel<<<(unsigned)((tot_i_sh + 255) / 256), 256, 0, s2>>>(Wgu_sh, pwgsh, IDIM / 4, tot_i_sh);
        long tot_i_ex = (long)NEXP * HDIM * (IDIM / 4);
        conv_inter_kernel<<<(unsigned)((tot_i_ex + 255) / 256), 256, 0, s2>>>(Wgu_ex, pwgex, IDIM / 4, tot_i_ex);
        long tot_p_sh = (long)IDIM * HDIM / 8;
        conv_plain_kernel<<<(unsigned)((tot_p_sh + 255) / 256), 256, 0, s2>>>(Wd_sh, pwdsh, tot_p_sh);
        long tot_p_ex = (long)NEXP * IDIM * HDIM / 8;
        conv_plain_kernel<<<(unsigned)((tot_p_ex + 255) / 256), 256, 0, s2>>>(Wd_ex, pwdex, tot_p_ex);
    }
    cudaEventRecord(ev_join, s2);

    // ---- main stream: attention + routing chain (no dependence on conversions) ----
    // 1. x = rmsnorm(hidden, ln1)
    rmsnorm_kernel<false><<<SEQ, 256>>>(hidden, ln1_w, nullptr, pxh, pxl);
    // 2. qkv = x @ Wqkv (3-pass)
    hf_gemm3<false, true><<<dim3(16, 8), 256, SM3_BYTES>>>(
        pxh, pxl, Wqkv, pqkv, nullptr, 2048, 1024);
    // 3. rope + qknorm + split
    rope_qk_kernel<<<dim3(SEQ, KVHEADS), 128>>>(cosb, sinb, qnorm_w, knorm_w);
    // 4. scores = q @ k^T (causal block-skip)
    sgemm_kernel<false, 1><<<dim3(8, 8, NHEADS), 256>>>(pq, pkT, pscores, nullptr,
        1024, 1024, 64, 64, 1024, 1024, 65536, 65536, 1048576, 2);
    // 5. causal softmax
    softmax_kernel<<<dim3(SEQ, NHEADS), 256>>>();
    // 6. attn = P @ V (K capped per row-block)
    sgemm_kernel<false, 2><<<dim3(1, 8, NHEADS), 256>>>(pscores, pv, pattn, nullptr,
        1024, 64, 1024, 1024, 64, 1024, 1048576, 65536, 64, 2);
    // 7. h1 = attn @ Wo + hidden (3-pass)
    hf_gemm3<true, false><<<dim3(8, 8), 256, SM3_BYTES>>>(
        pattn, nullptr, Wo, ph1, hidden, 1024, 1024);
    // 8. x2 = rmsnorm(h1, ln2)
    rmsnorm_kernel<true><<<SEQ, 256>>>(ph1, ln2_w, px2, px2h, px2l);
    // 12. logits = x2 @ Wgate (fp32)
    sgemm_kernel<false, 0><<<dim3(1, 8, 1), 256>>>(px2, Wgate, plog, nullptr,
        1024, 64, 1024, 1024, 64, 64, 0, 0, 0, 1);
    // 13. softmax + top8
    topk_kernel<<<SEQ, 64>>>();
    // 14. routing
    route_kernel<<<1, 64>>>();

    // ---- join: MoE path needs converted weights ----
    cudaStreamWaitEvent(0, ev_join, 0);

    // 9+10. hs = swiglu(x2 @ Wgu_shared)
    hf_gemm1b<0, true><<<dim3(48, 8), 256, SMP_BYTES>>>(px2h, pwgsh, nullptr, phsh, 6144, 1024);
    // 11. shared = hs @ Wd_shared
    hf_gemm1b<0, false><<<dim3(8, 8), 256, SMP_BYTES>>>(phsh, pwdsh, psh, nullptr, 1024, 3072);
    // 15+16. hexp = swiglu(gather(x2) @ Wgu_experts)
    hf_gemm1b<1, true><<<dim3(48, 256), 256, SMP_BYTES>>>(px2h, pwgex, nullptr, pheh, 6144, 1024);
    // 17. ye = hexp @ Wd_experts
    hf_gemm1b<2, false><<<dim3(8, 256), 256, SMP_BYTES>>>(pheh, pwdex, pye, nullptr, 1024, 3072);
    // 18. out = h1 + shared + moe
    combine_kernel<<<SEQ, 256>>>(out);
}